// round 9
// baseline (speedup 1.0000x reference)
#include <cuda_runtime.h>
#include <math.h>

// Problem shapes (fixed)
#define NB 512
#define NW 1024
#define NL 64
#define NJ 8
#define NI 32
#define NO 128
#define NK 2048   // L*I

// ---------------- device scratch (no allocations allowed) -------------------
__device__ float g_best[NJ * NB * NL];     // best[j][b][l]        (1 MB)
__device__ float g_cv  [NB * NI];          // body contribution    (64 KB)
__device__ float g_cvp [NJ * NB * NI];     // slot partials per j  (512 KB)
__device__ float g_conf[NB];               // exp(-total_mq)

// ---------------- packed f32x2 helpers (Blackwell FFMA2) --------------------
static __device__ __forceinline__ unsigned long long pk2(float x, float y) {
    unsigned long long r;
    asm("mov.b64 %0, {%1,%2};" : "=l"(r) : "f"(x), "f"(y));
    return r;
}
static __device__ __forceinline__ void fma2(unsigned long long& d,
                                            unsigned long long a,
                                            unsigned long long b) {
    asm("fma.rn.f32x2 %0, %1, %2, %0;" : "+l"(d) : "l"(a), "l"(b));
}
static __device__ __forceinline__ float2 up2(unsigned long long v) {
    float2 r;
    asm("mov.b64 {%0,%1}, %2;" : "=f"(r.x), "=f"(r.y) : "l"(v));
    return r;
}

// =============================================================================
// Kernel A: per-b fused  scores -> softmax -> best -> mq/conf -> body path
// grid = 512 CTAs (one per b), 256 threads.
// smem floats:
//   [0,1024)       coef2: 512 float2 {-2*w1*c, w1}   (as u64)
//   [1024,9216)    sc[8][1024]  scores -> unnormalized attn
//   [9216,25856)   tile 256 x 65 (padded wm chunk)
//   [25856,26368)  best_s[8][64]
//   [26368,..]     rz[8], mqs[8], As[8], gav[8], red[256]
// =============================================================================
#define OFF_COEF 0
#define OFF_SC   1024
#define OFF_TILE 9216
#define OFF_BEST (OFF_TILE + 256*65)      // 25856
#define OFF_RZ   (OFF_BEST + 512)         // 26368
#define OFF_MQS  (OFF_RZ + 8)
#define OFF_AS   (OFF_MQS + 8)
#define OFF_GAVG (OFF_AS + 8)
#define OFF_RED  (OFF_GAVG + 8)
#define SMEMA_FLOATS (OFF_RED + 256)      // 26656 floats = 106624 B

extern "C" __global__ void __launch_bounds__(256, 2)
kA(const float* __restrict__ wm, const float* __restrict__ constants,
   const float* __restrict__ gammas, const float* __restrict__ body_w,
   const float* __restrict__ body_b)
{
    extern __shared__ float sm[];
    float* sc   = sm + OFF_SC;
    float* tile = sm + OFF_TILE;
    float* best = sm + OFF_BEST;
    float* rz   = sm + OFF_RZ;
    float* mqs  = sm + OFF_MQS;
    float* As   = sm + OFF_AS;
    float* gav  = sm + OFF_GAVG;
    float* red  = sm + OFF_RED;
    unsigned long long* coef = (unsigned long long*)(sm + OFF_COEF);

    const int t    = threadIdx.x;
    const int b    = blockIdx.x;
    const int lane = t & 31;
    const int wid  = t >> 5;

    // ---- Phase 0: per-(j,l) coefficients (use sc as scratch) ----
    for (int e = t; e < NJ * NL; e += 256) {
        float g = gammas[e];
        g = fminf(fmaxf(g, 0.f), 1.f);
        float w1 = 1.f - g;
        float c  = constants[e];
        coef[e]      = pk2(-2.f * w1 * c, w1);
        sc[e]        = w1 * c * c;   // scratch for A_j
        sc[1024 + e] = g;            // scratch for g_avg
    }
    __syncthreads();
    if (t < NJ) {
        float a = 0.f, s = 0.f;
        for (int l = 0; l < NL; l++) { a += sc[t*64 + l]; s += sc[1024 + t*64 + l]; }
        As[t]  = a;
        gav[t] = s * (1.f / 64.f);
    }
    __syncthreads();

    float Areg[8];
#pragma unroll
    for (int j = 0; j < 8; j++) Areg[j] = As[j];

    const float* wmb = wm + (size_t)b * (NW * NL);

    // ---- Phase 1: scores for all (j,w), 4 chunks of 256 w ----
    for (int ch = 0; ch < 4; ch++) {
        const float4* src = (const float4*)(wmb + ch * 256 * 64);
#pragma unroll
        for (int q = 0; q < 16; q++) {
            int f = t + 256 * q;             // 0..4095 float4s
            int row = f >> 4, c4 = f & 15;
            float4 v = src[f];
            float* dst = tile + row * 65 + c4 * 4;
            dst[0] = v.x; dst[1] = v.y; dst[2] = v.z; dst[3] = v.w;
        }
        __syncthreads();

        unsigned long long acc[8];
        unsigned long long z0 = pk2(0.f, 0.f);
#pragma unroll
        for (int j = 0; j < 8; j++) acc[j] = z0;
        const float* myrow = tile + t * 65;
#pragma unroll 8
        for (int l = 0; l < 64; l++) {
            float x = myrow[l];
            unsigned long long a2 = pk2(x, x * x);
#pragma unroll
            for (int j = 0; j < 8; j++) fma2(acc[j], a2, coef[j * 64 + l]);
        }
#pragma unroll
        for (int j = 0; j < 8; j++) {
            float2 p = up2(acc[j]);
            sc[j * 1024 + ch * 256 + t] = Areg[j] + p.x + p.y;   // A -2cross +quad
        }
        __syncthreads();
    }

    // ---- Phase 2: softmax(-s) per j (warp wid owns j=wid) ----
    {
        const int j = wid;
        float mn = 3.4e38f;
        for (int w = lane; w < 1024; w += 32) mn = fminf(mn, sc[j*1024 + w]);
#pragma unroll
        for (int o = 16; o; o >>= 1) mn = fminf(mn, __shfl_xor_sync(0xffffffff, mn, o));
        float Z = 0.f, MQ = 0.f;
        for (int w = lane; w < 1024; w += 32) {
            float s = sc[j*1024 + w];
            float e = expf(mn - s);          // exp(-s - max(-s))
            sc[j*1024 + w] = e;              // unnormalized attn
            Z += e; MQ += e * s;
        }
#pragma unroll
        for (int o = 16; o; o >>= 1) {
            Z  += __shfl_xor_sync(0xffffffff, Z, o);
            MQ += __shfl_xor_sync(0xffffffff, MQ, o);
        }
        if (lane == 0) { rz[j] = 1.f / Z; mqs[j] = MQ / Z; }
    }
    __syncthreads();
    if (t == 0) {
        float tm = 0.f;
#pragma unroll
        for (int j = 0; j < 8; j++) tm += mqs[j];
        g_conf[b] = expf(-tm);
    }

    // ---- Phase 3: best[j][l] = (1/Z) * sum_w e * wm ----
    {
        const int j = wid;
        float a0 = 0.f, a1 = 0.f;
        for (int ch = 0; ch < 4; ch++) {
            __syncthreads();
            const float4* src = (const float4*)(wmb + ch * 256 * 64);
#pragma unroll
            for (int q = 0; q < 16; q++) {
                int f = t + 256 * q;
                int row = f >> 4, c4 = f & 15;
                float4 v = src[f];
                float* dst = tile + row * 65 + c4 * 4;
                dst[0] = v.x; dst[1] = v.y; dst[2] = v.z; dst[3] = v.w;
            }
            __syncthreads();
            const float* ew = sc + j * 1024 + ch * 256;
#pragma unroll 4
            for (int w = 0; w < 256; w++) {
                float aw = ew[w];
                a0 += aw * tile[w * 65 + lane];
                a1 += aw * tile[w * 65 + 32 + lane];
            }
        }
        float r = rz[wid];
        float b0v = a0 * r, b1v = a1 * r;
        best[j * 64 + lane]      = b0v;
        best[j * 64 + 32 + lane] = b1v;
        g_best[(j * NB + b) * 64 + lane]      = b0v;
        g_best[(j * NB + b) * 64 + 32 + lane] = b1v;
    }
    __syncthreads();

    // ---- Phase 4: body path: cv[b,i] = sum_j gavg_j*(best_j . body_w_ji + b_ji)
    {
        const int j = t >> 5, i = t & 31;
        const float* bwp = body_w + (j * NI + i) * NL;
        const float* bsp = best + j * 64;
        float d = 0.f;
#pragma unroll 8
        for (int l = 0; l < 64; l++) d += bsp[l] * bwp[l];
        d += body_b[j * NI + i];
        red[j * 32 + i] = gav[j] * d;
    }
    __syncthreads();
    if (t < 32) {
        float s = 0.f;
#pragma unroll
        for (int j = 0; j < 8; j++) s += red[j * 32 + t];
        g_cv[b * 32 + t] = s;
    }
}

// =============================================================================
// Kernel B: slot selector.  grid = (16 b-tiles of 32, 8 j), 256 threads.
// Per chunk of 256 k (= 8 l_slots): stage slot_w rows, compute logits into
// smem, per-(b,l) softmax over i=32, accumulate sum_l probs*best into regs.
// smem floats:
//   w_s    256*65 = 16640   (k-major, pad 65)
//   lg_s   256*33 = 8448    (logits [k][b], pad 33)
//   best_s 64*33  = 2112    ([l][b], pad 33)
//   sb_s   256
// =============================================================================
#define BOFF_W  0
#define BOFF_LG (256*65)
#define BOFF_BS (BOFF_LG + 256*33)
#define BOFF_SB (BOFF_BS + 64*33)
#define SMEMB_FLOATS (BOFF_SB + 256)   // 27456 floats = 109824 B

extern "C" __global__ void __launch_bounds__(256, 2)
kB(const float* __restrict__ slot_w, const float* __restrict__ slot_b)
{
    extern __shared__ float sm[];
    float* w_s = sm + BOFF_W;
    float* lg  = sm + BOFF_LG;
    float* bs  = sm + BOFF_BS;
    float* sb  = sm + BOFF_SB;

    const int t  = threadIdx.x;
    const int j  = blockIdx.y;
    const int b0 = blockIdx.x * 32;

    // load best tile transposed: bs[l*33 + b]
#pragma unroll
    for (int r = 0; r < 8; r++) {
        int e = t * 8 + r;               // 0..2047
        int bb = e >> 6, l = e & 63;
        bs[l * 33 + bb] = g_best[(j * NB + b0 + bb) * 64 + l];
    }

    const int q  = t & 7;                // b-quad (phase b)
    const int ko = t >> 3;               // k-oct  (phase b)
    const int cb = t & 31;               // b      (phase c)
    const int ls = t >> 5;               // l_slot (phase c)

    float accI[32];
#pragma unroll
    for (int i = 0; i < 32; i++) accI[i] = 0.f;

    const float* swj = slot_w + (size_t)j * (NK * NL);

    for (int ch = 0; ch < 8; ch++) {
        __syncthreads();
        sb[t] = slot_b[j * NK + ch * 256 + t];
        const float4* src = (const float4*)(swj + ch * 256 * 64);
#pragma unroll
        for (int qq = 0; qq < 16; qq++) {
            int f = t + 256 * qq;
            int row = f >> 4, c4 = f & 15;
            float4 v = src[f];
            float* dst = w_s + row * 65 + c4 * 4;
            dst[0] = v.x; dst[1] = v.y; dst[2] = v.z; dst[3] = v.w;
        }
        __syncthreads();

        // phase b: logits acc[4b][8k]
        float acc[4][8];
#pragma unroll
        for (int v = 0; v < 4; v++)
#pragma unroll
            for (int kk = 0; kk < 8; kk++) acc[v][kk] = sb[ko * 8 + kk];
#pragma unroll 4
        for (int l = 0; l < 64; l++) {
            float bb4[4];
#pragma unroll
            for (int v = 0; v < 4; v++) bb4[v] = bs[l * 33 + q * 4 + v];
            float ww[8];
#pragma unroll
            for (int kk = 0; kk < 8; kk++) ww[kk] = w_s[(ko * 8 + kk) * 65 + l];
#pragma unroll
            for (int v = 0; v < 4; v++)
#pragma unroll
                for (int kk = 0; kk < 8; kk++) acc[v][kk] += bb4[v] * ww[kk];
        }
#pragma unroll
        for (int kk = 0; kk < 8; kk++)
#pragma unroll
            for (int v = 0; v < 4; v++)
                lg[(ko * 8 + kk) * 33 + q * 4 + v] = acc[v][kk];
        __syncthreads();

        // phase c: softmax over i for (b=cb, l=ch*8+ls)
        {
            const int l = ch * 8 + ls;
            float m = -3.4e38f;
#pragma unroll
            for (int i = 0; i < 32; i++) m = fmaxf(m, lg[(ls * 32 + i) * 33 + cb]);
            float e[32];
            float Z = 0.f;
#pragma unroll
            for (int i = 0; i < 32; i++) {
                e[i] = expf(lg[(ls * 32 + i) * 33 + cb] - m);
                Z += e[i];
            }
            float s = bs[l * 33 + cb] / Z;
#pragma unroll
            for (int i = 0; i < 32; i++) accI[i] += e[i] * s;
        }
    }
    __syncthreads();

    // reduce accI over the 8 l_slot-threads per b (reuse w_s as scratch)
    float* red2 = w_s;
#pragma unroll
    for (int i = 0; i < 32; i++) red2[(ls * 32 + cb) * 32 + i] = accI[i];
    __syncthreads();
#pragma unroll
    for (int r = 0; r < 4; r++) {
        int e = t * 4 + r;               // 0..1023
        int bb = e >> 5, i = e & 31;
        float s = 0.f;
#pragma unroll
        for (int l8 = 0; l8 < 8; l8++) s += red2[(l8 * 32 + bb) * 32 + i];
        g_cvp[(j * NB + b0 + bb) * 32 + i] = s;
    }
}

// =============================================================================
// Kernel C: cv_total = body + sum_j slot partials; out = conf * (cv@W^T + b)
// grid = 512 (b), 128 threads (o).
// =============================================================================
extern "C" __global__ void __launch_bounds__(128)
kC(const float* __restrict__ head_w, const float* __restrict__ head_b,
   float* __restrict__ out)
{
    __shared__ float cvt[32];
    __shared__ float hw[NO * 33];        // pad 33 for conflict-free reads
    const int t = threadIdx.x;
    const int b = blockIdx.x;

#pragma unroll
    for (int r = 0; r < 32; r++) {
        int e = t + 128 * r;             // 0..4095
        int o = e >> 5, i = e & 31;
        hw[o * 33 + i] = head_w[e];
    }
    if (t < 32) {
        float v = g_cv[b * 32 + t];
#pragma unroll
        for (int j = 0; j < 8; j++) v += g_cvp[(j * NB + b) * 32 + t];
        cvt[t] = v;
    }
    __syncthreads();

    float d = head_b[t];
#pragma unroll
    for (int i = 0; i < 32; i++) d += cvt[i] * hw[t * 33 + i];
    out[b * NO + t] = g_conf[b] * d;
}

// =============================================================================
extern "C" void kernel_launch(void* const* d_in, const int* in_sizes, int n_in,
                              void* d_out, int out_size)
{
    const float* wm  = (const float*)d_in[0];
    const float* cst = (const float*)d_in[1];
    const float* gam = (const float*)d_in[2];
    const float* bw  = (const float*)d_in[3];
    const float* bb  = (const float*)d_in[4];
    const float* sw  = (const float*)d_in[5];
    const float* sb  = (const float*)d_in[6];
    const float* hwp = (const float*)d_in[7];
    const float* hbp = (const float*)d_in[8];
    float* out = (float*)d_out;

    cudaFuncSetAttribute(kA, cudaFuncAttributeMaxDynamicSharedMemorySize,
                         SMEMA_FLOATS * 4);
    cudaFuncSetAttribute(kB, cudaFuncAttributeMaxDynamicSharedMemorySize,
                         SMEMB_FLOATS * 4);

    kA<<<NB, 256, SMEMA_FLOATS * 4>>>(wm, cst, gam, bw, bb);
    dim3 gb(16, 8);
    kB<<<gb, 256, SMEMB_FLOATS * 4>>>(sw, sb);
    kC<<<NB, 128>>>(hwp, hbp, out);
}

// round 10
// speedup vs baseline: 1.4150x; 1.4150x over previous
#include <cuda_runtime.h>
#include <math.h>

// Problem shapes (fixed)
#define NB 512
#define NW 1024
#define NL 64
#define NJ 8
#define NI 32
#define NO 128
#define NK 2048   // L*I

// ---------------- device scratch (no allocations allowed) -------------------
__device__ float g_best[NJ * NB * NL];     // best[j][b][l]        (1 MB)
__device__ float g_cv  [NB * NI];          // body contribution    (64 KB)
__device__ float g_cvp [NJ * NB * NI];     // slot partials per j  (512 KB)
__device__ float g_conf[NB];               // exp(-total_mq)

// ---------------- packed f32x2 helpers (Blackwell FFMA2) --------------------
static __device__ __forceinline__ unsigned long long pk2(float x, float y) {
    unsigned long long r;
    asm("mov.b64 %0, {%1,%2};" : "=l"(r) : "f"(x), "f"(y));
    return r;
}
static __device__ __forceinline__ void fma2(unsigned long long& d,
                                            unsigned long long a,
                                            unsigned long long b) {
    asm("fma.rn.f32x2 %0, %1, %2, %0;" : "+l"(d) : "l"(a), "l"(b));
}
static __device__ __forceinline__ float2 up2(unsigned long long v) {
    float2 r;
    asm("mov.b64 {%0,%1}, %2;" : "=f"(r.x), "=f"(r.y) : "l"(v));
    return r;
}

// =============================================================================
// Kernel A: per-b fused  scores -> softmax -> best -> mq/conf -> body path
// grid = 512 CTAs (one per b), 256 threads.
// smem floats:
//   OFF_COEF  coefT u64[64][8]  {-2*w1*c, w1}        (1024 floats)
//   OFF_SC    sc[1024][8]   scores -> unnorm attn    (8192 floats)
//   OFF_TILE  tile 256 x 65 padded wm chunk          (16640 floats)
//   OFF_BEST  best_s[8][64]                          (512)
//   rz[8], mqs[8], As[8], gav[8], wredm/z/q[64 ea], mnf[8]
// =============================================================================
#define OFF_COEF  0
#define OFF_SC    1024
#define OFF_TILE  (OFF_SC + 1024*8)          // 9216
#define OFF_BEST  (OFF_TILE + 256*65)        // 25856
#define OFF_RZ    (OFF_BEST + 512)           // 26368
#define OFF_MQS   (OFF_RZ + 8)
#define OFF_AS    (OFF_MQS + 8)
#define OFF_GAV   (OFF_AS + 8)
#define OFF_WREDM (OFF_GAV + 8)              // 8 warps x 8 j
#define OFF_WREDZ (OFF_WREDM + 64)
#define OFF_WREDQ (OFF_WREDZ + 64)
#define OFF_MNF   (OFF_WREDQ + 64)
#define SMEMA_FLOATS (OFF_MNF + 8)           // 26600 floats = 106400 B

extern "C" __global__ void __launch_bounds__(256, 2)
kA(const float* __restrict__ wm, const float* __restrict__ constants,
   const float* __restrict__ gammas, const float* __restrict__ body_w,
   const float* __restrict__ body_b)
{
    extern __shared__ float sm[];
    unsigned long long* coefT = (unsigned long long*)(sm + OFF_COEF); // [l*8+j]
    float* sc   = sm + OFF_SC;
    float* tile = sm + OFF_TILE;
    float* best = sm + OFF_BEST;
    float* rz   = sm + OFF_RZ;
    float* mqs  = sm + OFF_MQS;
    float* As   = sm + OFF_AS;
    float* gav  = sm + OFF_GAV;
    float* wredm= sm + OFF_WREDM;
    float* wredz= sm + OFF_WREDZ;
    float* wredq= sm + OFF_WREDQ;
    float* mnf  = sm + OFF_MNF;

    const int t    = threadIdx.x;
    const int b    = blockIdx.x;
    const int lane = t & 31;
    const int wid  = t >> 5;

    // ---- Phase 0: per-(j,l) coefficients (use sc as scratch) ----
    for (int e = t; e < NJ * NL; e += 256) {
        int j = e >> 6, l = e & 63;
        float g = gammas[e];
        g = fminf(fmaxf(g, 0.f), 1.f);
        float w1 = 1.f - g;
        float c  = constants[e];
        coefT[l * 8 + j] = pk2(-2.f * w1 * c, w1);
        sc[e]        = w1 * c * c;   // scratch for A_j
        sc[1024 + e] = g;            // scratch for g_avg
    }
    __syncthreads();
    if (t < NJ) {
        float a = 0.f, s = 0.f;
        for (int l = 0; l < NL; l++) { a += sc[t*64 + l]; s += sc[1024 + t*64 + l]; }
        As[t]  = a;
        gav[t] = s * (1.f / 64.f);
    }
    __syncthreads();

    const float* wmb = wm + (size_t)b * (NW * NL);

    // ---- Phase 1: scores. Thread tile: W=2 (wp, wp+128), J=4 (jh*4..+3) ----
    {
        const int wp = t & 127;
        const int jh = t >> 7;
        float Areg[4];
#pragma unroll
        for (int k = 0; k < 4; k++) Areg[k] = As[jh * 4 + k];
        const ulonglong2* cT = (const ulonglong2*)coefT;   // index l*4 + 2jh

        for (int ch = 0; ch < 4; ch++) {
            const float4* src = (const float4*)(wmb + ch * 256 * 64);
#pragma unroll
            for (int q = 0; q < 16; q++) {
                int f = t + 256 * q;             // 0..4095 float4s
                int row = f >> 4, c4 = f & 15;
                float4 v = src[f];
                float* dst = tile + row * 65 + c4 * 4;
                dst[0] = v.x; dst[1] = v.y; dst[2] = v.z; dst[3] = v.w;
            }
            __syncthreads();

            unsigned long long acc0[4], acc1[4];
#pragma unroll
            for (int k = 0; k < 4; k++) {
                acc0[k] = pk2(Areg[k], 0.f);
                acc1[k] = pk2(Areg[k], 0.f);
            }
            const float* r0 = tile + wp * 65;
            const float* r1 = tile + (wp + 128) * 65;
#pragma unroll 8
            for (int l = 0; l < 64; l++) {
                float x0 = r0[l];
                float x1 = r1[l];
                ulonglong2 c01 = cT[l * 4 + 2 * jh];
                ulonglong2 c23 = cT[l * 4 + 2 * jh + 1];
                unsigned long long a0 = pk2(x0, x0 * x0);
                unsigned long long a1 = pk2(x1, x1 * x1);
                fma2(acc0[0], a0, c01.x); fma2(acc0[1], a0, c01.y);
                fma2(acc0[2], a0, c23.x); fma2(acc0[3], a0, c23.y);
                fma2(acc1[0], a1, c01.x); fma2(acc1[1], a1, c01.y);
                fma2(acc1[2], a1, c23.x); fma2(acc1[3], a1, c23.y);
            }
            int gw0 = ch * 256 + wp;
            float4 o0, o1;
            { float2 p = up2(acc0[0]); o0.x = p.x + p.y; }
            { float2 p = up2(acc0[1]); o0.y = p.x + p.y; }
            { float2 p = up2(acc0[2]); o0.z = p.x + p.y; }
            { float2 p = up2(acc0[3]); o0.w = p.x + p.y; }
            { float2 p = up2(acc1[0]); o1.x = p.x + p.y; }
            { float2 p = up2(acc1[1]); o1.y = p.x + p.y; }
            { float2 p = up2(acc1[2]); o1.z = p.x + p.y; }
            { float2 p = up2(acc1[3]); o1.w = p.x + p.y; }
            *(float4*)(sc + gw0 * 8 + 4 * jh)         = o0;
            *(float4*)(sc + (gw0 + 128) * 8 + 4 * jh) = o1;
            __syncthreads();
        }
    }

    // ---- Phase 2: softmax(-s) per j, row-based (warp owns 128-w slice) ----
    {
        const int wbase = wid * 128 + lane;
        float mn8[8];
#pragma unroll
        for (int j = 0; j < 8; j++) mn8[j] = 3.4e38f;
#pragma unroll
        for (int k = 0; k < 4; k++) {
            int w = wbase + k * 32;
            float4 a  = *(const float4*)(sc + w * 8);
            float4 b4 = *(const float4*)(sc + w * 8 + 4);
            mn8[0] = fminf(mn8[0], a.x);  mn8[1] = fminf(mn8[1], a.y);
            mn8[2] = fminf(mn8[2], a.z);  mn8[3] = fminf(mn8[3], a.w);
            mn8[4] = fminf(mn8[4], b4.x); mn8[5] = fminf(mn8[5], b4.y);
            mn8[6] = fminf(mn8[6], b4.z); mn8[7] = fminf(mn8[7], b4.w);
        }
#pragma unroll
        for (int o = 16; o; o >>= 1)
#pragma unroll
            for (int j = 0; j < 8; j++)
                mn8[j] = fminf(mn8[j], __shfl_xor_sync(0xffffffffu, mn8[j], o));
        if (lane == 0) {
#pragma unroll
            for (int j = 0; j < 8; j++) wredm[wid * 8 + j] = mn8[j];
        }
    }
    __syncthreads();
    if (t < 8) {
        float m = 3.4e38f;
#pragma unroll
        for (int w8 = 0; w8 < 8; w8++) m = fminf(m, wredm[w8 * 8 + t]);
        mnf[t] = m;
    }
    __syncthreads();
    {
        const int wbase = wid * 128 + lane;
        float f8[8], Z8[8], Q8[8];
#pragma unroll
        for (int j = 0; j < 8; j++) { f8[j] = mnf[j]; Z8[j] = 0.f; Q8[j] = 0.f; }
#pragma unroll
        for (int k = 0; k < 4; k++) {
            int w = wbase + k * 32;
            float4 a  = *(const float4*)(sc + w * 8);
            float4 b4 = *(const float4*)(sc + w * 8 + 4);
            float s[8] = {a.x, a.y, a.z, a.w, b4.x, b4.y, b4.z, b4.w};
            float e[8];
#pragma unroll
            for (int j = 0; j < 8; j++) {
                e[j] = expf(f8[j] - s[j]);
                Z8[j] += e[j];
                Q8[j] += e[j] * s[j];
            }
            a.x = e[0]; a.y = e[1]; a.z = e[2]; a.w = e[3];
            b4.x = e[4]; b4.y = e[5]; b4.z = e[6]; b4.w = e[7];
            *(float4*)(sc + w * 8)     = a;
            *(float4*)(sc + w * 8 + 4) = b4;
        }
#pragma unroll
        for (int o = 16; o; o >>= 1)
#pragma unroll
            for (int j = 0; j < 8; j++) {
                Z8[j] += __shfl_xor_sync(0xffffffffu, Z8[j], o);
                Q8[j] += __shfl_xor_sync(0xffffffffu, Q8[j], o);
            }
        if (lane == 0) {
#pragma unroll
            for (int j = 0; j < 8; j++) { wredz[wid*8 + j] = Z8[j]; wredq[wid*8 + j] = Q8[j]; }
        }
    }
    __syncthreads();
    if (t < 8) {
        float Z = 0.f, Q = 0.f;
#pragma unroll
        for (int w8 = 0; w8 < 8; w8++) { Z += wredz[w8*8 + t]; Q += wredq[w8*8 + t]; }
        rz[t]  = 1.f / Z;
        mqs[t] = Q / Z;
    }
    __syncthreads();
    if (t == 0) {
        float tm = 0.f;
#pragma unroll
        for (int j = 0; j < 8; j++) tm += mqs[j];
        g_conf[b] = expf(-tm);
    }

    // ---- Phase 3: best. Warp owns 32-w slice per chunk, all 8 j in regs ----
    {
        float accA[8], accB[8];
#pragma unroll
        for (int j = 0; j < 8; j++) { accA[j] = 0.f; accB[j] = 0.f; }
        const int wl0 = wid * 32;

        for (int ch = 0; ch < 4; ch++) {
            __syncthreads();
            const float4* src = (const float4*)(wmb + ch * 256 * 64);
#pragma unroll
            for (int q = 0; q < 16; q++) {
                int f = t + 256 * q;
                int row = f >> 4, c4 = f & 15;
                float4 v = src[f];
                float* dst = tile + row * 65 + c4 * 4;
                dst[0] = v.x; dst[1] = v.y; dst[2] = v.z; dst[3] = v.w;
            }
            __syncthreads();
#pragma unroll 4
            for (int i = 0; i < 32; i++) {
                int wl = wl0 + i;
                int gw = ch * 256 + wl;
                float4 a  = *(const float4*)(sc + gw * 8);
                float4 b4 = *(const float4*)(sc + gw * 8 + 4);
                float x0 = tile[wl * 65 + lane];
                float x1 = tile[wl * 65 + 32 + lane];
                accA[0] += a.x  * x0; accB[0] += a.x  * x1;
                accA[1] += a.y  * x0; accB[1] += a.y  * x1;
                accA[2] += a.z  * x0; accB[2] += a.z  * x1;
                accA[3] += a.w  * x0; accB[3] += a.w  * x1;
                accA[4] += b4.x * x0; accB[4] += b4.x * x1;
                accA[5] += b4.y * x0; accB[5] += b4.y * x1;
                accA[6] += b4.z * x0; accB[6] += b4.z * x1;
                accA[7] += b4.w * x0; accB[7] += b4.w * x1;
            }
        }
        __syncthreads();            // all attn reads done; reuse sc as scratch
        float* red = sc;
#pragma unroll
        for (int j = 0; j < 8; j++) {
            red[(wid * 8 + j) * 64 + lane]      = accA[j];
            red[(wid * 8 + j) * 64 + 32 + lane] = accB[j];
        }
    }
    __syncthreads();
    {
        const int j = t >> 5;
        float s0 = 0.f, s1 = 0.f;
        const float* red = sc;
#pragma unroll
        for (int w8 = 0; w8 < 8; w8++) {
            s0 += red[(w8 * 8 + j) * 64 + lane];
            s1 += red[(w8 * 8 + j) * 64 + 32 + lane];
        }
        float r = rz[j];
        s0 *= r; s1 *= r;
        best[j * 64 + lane]      = s0;
        best[j * 64 + 32 + lane] = s1;
        g_best[(j * NB + b) * 64 + lane]      = s0;
        g_best[(j * NB + b) * 64 + 32 + lane] = s1;
    }
    __syncthreads();

    // ---- Phase 4: body path ----
    {
        const int j = t >> 5, i = t & 31;
        const float4* bwp = (const float4*)(body_w + (j * NI + i) * NL);
        const float4* bsp = (const float4*)(best + j * 64);
        float d = 0.f;
#pragma unroll
        for (int l4 = 0; l4 < 16; l4++) {
            float4 w4 = bwp[l4];
            float4 x4 = bsp[l4];
            d += x4.x * w4.x + x4.y * w4.y + x4.z * w4.z + x4.w * w4.w;
        }
        d += body_b[j * NI + i];
        sc[j * 32 + i] = gav[j] * d;     // reuse sc as scratch
    }
    __syncthreads();
    if (t < 32) {
        float s = 0.f;
#pragma unroll
        for (int j = 0; j < 8; j++) s += sc[j * 32 + t];
        g_cv[b * 32 + t] = s;
    }
}

// =============================================================================
// Kernel B: slot selector.  grid = (16 b-tiles of 32, 8 j), 256 threads.
// Thread tile 8b x 4k with FFMA2 (best staged [l][b] pad 36 -> ulonglong2).
// smem floats: w_s 256*65, lg 256*36, bs 64*36, sb 256
// =============================================================================
#define BOFF_W  0
#define BOFF_LG (256*65)                   // 16640
#define BOFF_BS (BOFF_LG + 256*36)         // 25856
#define BOFF_SB (BOFF_BS + 64*36)          // 28160
#define SMEMB_FLOATS (BOFF_SB + 256)       // 28416 floats = 113664 B

extern "C" __global__ void __launch_bounds__(256, 1)
kB(const float* __restrict__ slot_w, const float* __restrict__ slot_b)
{
    extern __shared__ float sm[];
    float* w_s = sm + BOFF_W;
    float* lg  = sm + BOFF_LG;
    float* bs  = sm + BOFF_BS;
    float* sb  = sm + BOFF_SB;

    const int t  = threadIdx.x;
    const int j  = blockIdx.y;
    const int b0 = blockIdx.x * 32;

    const int q  = t & 3;                // b-octet (phase b): b = q*8..q*8+7
    const int ko = t >> 2;               // k-quad  (phase b): k = ko*4+kk
    const int cb = t & 31;               // b       (phase c)
    const int ls = t >> 5;               // l_slot  (phase c)

    // stage best tile transposed: bs[l*36 + b]
#pragma unroll
    for (int r = 0; r < 8; r++) {
        int e = t * 8 + r;               // 0..2047
        int bb = e >> 6, l = e & 63;
        bs[l * 36 + bb] = g_best[(j * NB + b0 + bb) * 64 + l];
    }

    float accI[32];
#pragma unroll
    for (int i = 0; i < 32; i++) accI[i] = 0.f;

    const float* swj = slot_w + (size_t)j * (NK * NL);

    for (int ch = 0; ch < 8; ch++) {
        __syncthreads();
        sb[t] = slot_b[j * NK + ch * 256 + t];
        const float4* src = (const float4*)(swj + ch * 256 * 64);
#pragma unroll
        for (int qq = 0; qq < 16; qq++) {
            int f = t + 256 * qq;
            int row = f >> 4, c4 = f & 15;
            float4 v = src[f];
            float* dst = w_s + row * 65 + c4 * 4;
            dst[0] = v.x; dst[1] = v.y; dst[2] = v.z; dst[3] = v.w;
        }
        __syncthreads();

        // phase b: logits acc2[4 kk][4 b-pairs] (f32x2)
        unsigned long long acc2[4][4];
#pragma unroll
        for (int kk = 0; kk < 4; kk++) {
            float sv = sb[ko * 4 + kk];
            unsigned long long p = pk2(sv, sv);
#pragma unroll
            for (int bp = 0; bp < 4; bp++) acc2[kk][bp] = p;
        }
#pragma unroll 8
        for (int l = 0; l < 64; l++) {
            ulonglong2 p0 = *(const ulonglong2*)(bs + l * 36 + q * 8);
            ulonglong2 p1 = *(const ulonglong2*)(bs + l * 36 + q * 8 + 4);
#pragma unroll
            for (int kk = 0; kk < 4; kk++) {
                float w = w_s[(ko * 4 + kk) * 65 + l];
                unsigned long long w2 = pk2(w, w);
                fma2(acc2[kk][0], p0.x, w2);
                fma2(acc2[kk][1], p0.y, w2);
                fma2(acc2[kk][2], p1.x, w2);
                fma2(acc2[kk][3], p1.y, w2);
            }
        }
#pragma unroll
        for (int kk = 0; kk < 4; kk++) {
            int k = ko * 4 + kk;
            ulonglong2 o0; o0.x = acc2[kk][0]; o0.y = acc2[kk][1];
            ulonglong2 o1; o1.x = acc2[kk][2]; o1.y = acc2[kk][3];
            *(ulonglong2*)(lg + k * 36 + q * 8)     = o0;
            *(ulonglong2*)(lg + k * 36 + q * 8 + 4) = o1;
        }
        __syncthreads();

        // phase c: softmax over i for (b=cb, l=ch*8+ls)
        {
            const int l = ch * 8 + ls;
            float lv[32];
            float m = -3.4e38f;
#pragma unroll
            for (int i = 0; i < 32; i++) {
                lv[i] = lg[(ls * 32 + i) * 36 + cb];
                m = fmaxf(m, lv[i]);
            }
            float Z = 0.f;
#pragma unroll
            for (int i = 0; i < 32; i++) {
                lv[i] = expf(lv[i] - m);
                Z += lv[i];
            }
            float s = bs[l * 36 + cb] / Z;
#pragma unroll
            for (int i = 0; i < 32; i++) accI[i] += lv[i] * s;
        }
    }
    __syncthreads();

    // reduce accI over the 8 l_slot-threads per b (reuse w_s; pad 33)
    float* red2 = w_s;
#pragma unroll
    for (int i = 0; i < 32; i++) red2[(ls * 32 + cb) * 33 + i] = accI[i];
    __syncthreads();
#pragma unroll
    for (int r = 0; r < 4; r++) {
        int e = t * 4 + r;               // 0..1023
        int bb = e >> 5, i = e & 31;
        float s = 0.f;
#pragma unroll
        for (int l8 = 0; l8 < 8; l8++) s += red2[(l8 * 32 + bb) * 33 + i];
        g_cvp[(j * NB + b0 + bb) * 32 + i] = s;
    }
}

// =============================================================================
// Kernel C: cv_total = body + sum_j slot partials; out = conf * (cv@W^T + b)
// =============================================================================
extern "C" __global__ void __launch_bounds__(128)
kC(const float* __restrict__ head_w, const float* __restrict__ head_b,
   float* __restrict__ out)
{
    __shared__ float cvt[32];
    __shared__ float hw[NO * 33];
    const int t = threadIdx.x;
    const int b = blockIdx.x;

#pragma unroll
    for (int r = 0; r < 32; r++) {
        int e = t + 128 * r;             // 0..4095
        int o = e >> 5, i = e & 31;
        hw[o * 33 + i] = head_w[e];
    }
    if (t < 32) {
        float v = g_cv[b * 32 + t];
#pragma unroll
        for (int j = 0; j < 8; j++) v += g_cvp[(j * NB + b) * 32 + t];
        cvt[t] = v;
    }
    __syncthreads();

    float d = head_b[t];
#pragma unroll
    for (int i = 0; i < 32; i++) d += cvt[i] * hw[t * 33 + i];
    out[b * NO + t] = g_conf[b] * d;
}

// =============================================================================
extern "C" void kernel_launch(void* const* d_in, const int* in_sizes, int n_in,
                              void* d_out, int out_size)
{
    const float* wm  = (const float*)d_in[0];
    const float* cst = (const float*)d_in[1];
    const float* gam = (const float*)d_in[2];
    const float* bw  = (const float*)d_in[3];
    const float* bb  = (const float*)d_in[4];
    const float* sw  = (const float*)d_in[5];
    const float* sb  = (const float*)d_in[6];
    const float* hwp = (const float*)d_in[7];
    const float* hbp = (const float*)d_in[8];
    float* out = (float*)d_out;

    cudaFuncSetAttribute(kA, cudaFuncAttributeMaxDynamicSharedMemorySize,
                         SMEMA_FLOATS * 4);
    cudaFuncSetAttribute(kB, cudaFuncAttributeMaxDynamicSharedMemorySize,
                         SMEMB_FLOATS * 4);

    kA<<<NB, 256, SMEMA_FLOATS * 4>>>(wm, cst, gam, bw, bb);
    dim3 gb(16, 8);
    kB<<<gb, 256, SMEMB_FLOATS * 4>>>(sw, sb);
    kC<<<NB, 128>>>(hwp, hbp, out);
}

// round 11
// speedup vs baseline: 1.5890x; 1.1230x over previous
#include <cuda_runtime.h>
#include <math.h>

// Problem shapes (fixed)
#define NB 512
#define NW 1024
#define NL 64
#define NJ 8
#define NI 32
#define NO 128
#define NK 2048   // L*I

// ---------------- device scratch (no allocations allowed) -------------------
__device__ float g_best[NJ * NB * NL];       // best[j][b][l]        (1 MB)
__device__ float g_cv  [NB * NI];            // body contribution
__device__ float g_cvp [2 * NJ * NB * NI];   // slot partials [kh][j][b][i]
__device__ float g_conf[NB];                 // exp(-total_mq)

// ---------------- packed f32x2 helpers (Blackwell FFMA2) --------------------
static __device__ __forceinline__ unsigned long long pk2(float x, float y) {
    unsigned long long r;
    asm("mov.b64 %0, {%1,%2};" : "=l"(r) : "f"(x), "f"(y));
    return r;
}
static __device__ __forceinline__ void fma2(unsigned long long& d,
                                            unsigned long long a,
                                            unsigned long long b) {
    asm("fma.rn.f32x2 %0, %1, %2, %0;" : "+l"(d) : "l"(a), "l"(b));
}
static __device__ __forceinline__ float2 up2(unsigned long long v) {
    float2 r;
    asm("mov.b64 {%0,%1}, %2;" : "=f"(r.x), "=f"(r.y) : "l"(v));
    return r;
}

// =============================================================================
// Kernel A: per-b fully fused, single wm staging, streaming softmax with a
// fixed exp-offset C_j = min(scores of chunk 0).
// grid = 512 CTAs (one per b), 256 threads, 8 chunks of 128 w.
// smem (floats):
//   A_COEF  coefT u64[64][8] {-2*w1*c, w1}      1024
//   A_TILE  tile[128][65] wm chunk              8320   (reused as reduce buf)
//   A_SCB   scb[128][8]  chunk scores/attn      1024   (reused: best + body red)
//   misc    As,gav,Cs,rz,mqs (8 ea) + zw,qw (16 ea)
// total 10440 floats = 41760 B -> 5 CTAs/SM
// =============================================================================
#define CW     128
#define A_COEF 0
#define A_TILE 1024
#define A_SCB  (A_TILE + 128*65)      // 9344
#define A_AS   (A_SCB + 1024)         // 10368
#define A_GAV  (A_AS + 8)
#define A_CS   (A_GAV + 8)
#define A_RZ   (A_CS + 8)
#define A_MQS  (A_RZ + 8)
#define A_ZW   (A_MQS + 8)            // 8 warps x 2
#define A_QW   (A_ZW + 16)
#define A_SMEM_FLOATS (A_QW + 16)     // 10440

extern "C" __global__ void __launch_bounds__(256, 5)
kA(const float* __restrict__ wm, const float* __restrict__ constants,
   const float* __restrict__ gammas, const float* __restrict__ body_w,
   const float* __restrict__ body_b)
{
    extern __shared__ float sm[];
    unsigned long long* coefT = (unsigned long long*)(sm + A_COEF); // [l*8+j]
    float* tile = sm + A_TILE;
    float* scb  = sm + A_SCB;
    float* As   = sm + A_AS;
    float* gav  = sm + A_GAV;
    float* Cs   = sm + A_CS;
    float* rz   = sm + A_RZ;
    float* mqs  = sm + A_MQS;
    float* zw   = sm + A_ZW;
    float* qw   = sm + A_QW;

    const int t    = threadIdx.x;
    const int b    = blockIdx.x;
    const int lane = t & 31;
    const int wid  = t >> 5;
    const int wp   = t & 63;          // score tiling: w in {wp, wp+64}
    const int jp   = t >> 6;          // j in {2jp, 2jp+1}

    // ---- Phase 0: coefficients (scratch in tile) ----
    for (int e = t; e < NJ * NL; e += 256) {
        int j = e >> 6, l = e & 63;
        float g = gammas[e];
        g = fminf(fmaxf(g, 0.f), 1.f);
        float w1 = 1.f - g;
        float c  = constants[e];
        coefT[l * 8 + j] = pk2(-2.f * w1 * c, w1);
        tile[e]       = w1 * c * c;
        tile[512 + e] = g;
    }
    __syncthreads();
    if (t < 8) {
        float a = 0.f, s = 0.f;
        for (int l = 0; l < NL; l++) { a += tile[t*64 + l]; s += tile[512 + t*64 + l]; }
        As[t]  = a;
        gav[t] = s * (1.f / 64.f);
    }
    __syncthreads();

    const float A0 = As[2*jp], A1 = As[2*jp + 1];
    const ulonglong2* cT = (const ulonglong2*)coefT;   // index l*4 + jp
    const float* wmb = wm + (size_t)b * (NW * NL);

    unsigned long long acc2[8];                        // best accum (l, l+32)
#pragma unroll
    for (int j = 0; j < 8; j++) acc2[j] = pk2(0.f, 0.f);
    float zp0 = 0.f, zp1 = 0.f, qp0 = 0.f, qp1 = 0.f;  // Z/MQ partials
    float c0 = 0.f, c1 = 0.f;                          // exp offsets (set @ch0)

    for (int ch = 0; ch < 8; ch++) {
        __syncthreads();
        // ---- stage 128-w chunk ----
        const float4* src = (const float4*)(wmb + ch * CW * 64);
#pragma unroll
        for (int qq = 0; qq < 8; qq++) {
            int f = t + 256 * qq;            // 0..2047 float4s
            int row = f >> 4, c4 = f & 15;
            float4 v = src[f];
            float* dst = tile + row * 65 + c4 * 4;
            dst[0] = v.x; dst[1] = v.y; dst[2] = v.z; dst[3] = v.w;
        }
        __syncthreads();

        // ---- scores for (w in {wp,wp+64}) x (j in {2jp,2jp+1}) ----
        unsigned long long s00 = pk2(0.f, 0.f), s01 = s00, s10 = s00, s11 = s00;
        const float* r0 = tile + wp * 65;
        const float* r1 = tile + (wp + 64) * 65;
#pragma unroll 8
        for (int l = 0; l < 64; l++) {
            float x0 = r0[l], x1 = r1[l];
            ulonglong2 cc = cT[l * 4 + jp];
            unsigned long long a0 = pk2(x0, x0 * x0);
            unsigned long long a1 = pk2(x1, x1 * x1);
            fma2(s00, a0, cc.x); fma2(s01, a0, cc.y);
            fma2(s10, a1, cc.x); fma2(s11, a1, cc.y);
        }
        float sv0, sv1, sv2, sv3;
        { float2 p = up2(s00); sv0 = A0 + p.x + p.y; }
        { float2 p = up2(s01); sv1 = A1 + p.x + p.y; }
        { float2 p = up2(s10); sv2 = A0 + p.x + p.y; }
        { float2 p = up2(s11); sv3 = A1 + p.x + p.y; }

        if (ch == 0) {
            // establish exp offsets C_j = min over chunk-0 scores
            *(float2*)(scb + wp * 8 + 2 * jp)        = make_float2(sv0, sv1);
            *(float2*)(scb + (wp + 64) * 8 + 2 * jp) = make_float2(sv2, sv3);
            __syncthreads();
            float mn = 3.4e38f;
#pragma unroll
            for (int r = 0; r < 4; r++)
                mn = fminf(mn, scb[(lane + 32 * r) * 8 + wid]);
#pragma unroll
            for (int o = 16; o; o >>= 1)
                mn = fminf(mn, __shfl_xor_sync(0xffffffffu, mn, o));
            if (lane == 0) Cs[wid] = mn;
            __syncthreads();
            c0 = Cs[2 * jp]; c1 = Cs[2 * jp + 1];
        }

        float e0 = expf(c0 - sv0), e1 = expf(c1 - sv1);
        float e2 = expf(c0 - sv2), e3 = expf(c1 - sv3);
        zp0 += e0 + e2;            zp1 += e1 + e3;
        qp0 += e0 * sv0 + e2 * sv2; qp1 += e1 * sv1 + e3 * sv3;
        *(float2*)(scb + wp * 8 + 2 * jp)        = make_float2(e0, e1);
        *(float2*)(scb + (wp + 64) * 8 + 2 * jp) = make_float2(e2, e3);
        __syncthreads();

        // ---- accumulate best: warp owns 16-w slice, all 8 j, f32x2 packed --
        const int w0 = wid * 16;
#pragma unroll 4
        for (int i = 0; i < 16; i++) {
            int wl = w0 + i;
            float4 a  = *(const float4*)(scb + wl * 8);
            float4 b4 = *(const float4*)(scb + wl * 8 + 4);
            float x0 = tile[wl * 65 + lane];
            float x1 = tile[wl * 65 + 32 + lane];
            unsigned long long xx = pk2(x0, x1);
            fma2(acc2[0], xx, pk2(a.x,  a.x));
            fma2(acc2[1], xx, pk2(a.y,  a.y));
            fma2(acc2[2], xx, pk2(a.z,  a.z));
            fma2(acc2[3], xx, pk2(a.w,  a.w));
            fma2(acc2[4], xx, pk2(b4.x, b4.x));
            fma2(acc2[5], xx, pk2(b4.y, b4.y));
            fma2(acc2[6], xx, pk2(b4.z, b4.z));
            fma2(acc2[7], xx, pk2(b4.w, b4.w));
        }
    }

    // ---- Z/MQ reduction ----
#pragma unroll
    for (int o = 16; o; o >>= 1) {
        zp0 += __shfl_xor_sync(0xffffffffu, zp0, o);
        zp1 += __shfl_xor_sync(0xffffffffu, zp1, o);
        qp0 += __shfl_xor_sync(0xffffffffu, qp0, o);
        qp1 += __shfl_xor_sync(0xffffffffu, qp1, o);
    }
    __syncthreads();                       // last accumulate done; reuse tile
    if (lane == 0) {
        zw[wid * 2] = zp0; zw[wid * 2 + 1] = zp1;
        qw[wid * 2] = qp0; qw[wid * 2 + 1] = qp1;
    }
    // dump best partials (warp-sliced) into tile
    float* red = tile;
#pragma unroll
    for (int j = 0; j < 8; j++) {
        float2 p = up2(acc2[j]);
        red[(wid * 8 + j) * 64 + lane]      = p.x;
        red[(wid * 8 + j) * 64 + 32 + lane] = p.y;
    }
    __syncthreads();
    if (t < 8) {
        int j = t, hp = j >> 1, k = j & 1;     // warps 2hp,2hp+1 hold j
        float Z = zw[(2*hp) * 2 + k] + zw[(2*hp + 1) * 2 + k];
        float Q = qw[(2*hp) * 2 + k] + qw[(2*hp + 1) * 2 + k];
        rz[j]  = 1.f / Z;
        mqs[j] = Q / Z;
    }
    __syncthreads();
    if (t == 0) {
        float tm = 0.f;
#pragma unroll
        for (int j = 0; j < 8; j++) tm += mqs[j];
        g_conf[b] = expf(-tm);
    }
    // ---- best finalize (scb reused as best buffer) ----
    {
        const int j = t >> 5;
        float s0 = 0.f, s1 = 0.f;
#pragma unroll
        for (int w8 = 0; w8 < 8; w8++) {
            s0 += red[(w8 * 8 + j) * 64 + lane];
            s1 += red[(w8 * 8 + j) * 64 + 32 + lane];
        }
        float r = rz[j];
        s0 *= r; s1 *= r;
        scb[j * 64 + lane]      = s0;
        scb[j * 64 + 32 + lane] = s1;
        g_best[((size_t)j * NB + b) * 64 + lane]      = s0;
        g_best[((size_t)j * NB + b) * 64 + 32 + lane] = s1;
    }
    __syncthreads();

    // ---- body path ----
    {
        const int j = t >> 5, i = t & 31;
        const float4* bwp = (const float4*)(body_w + (j * NI + i) * NL);
        const float4* bsp = (const float4*)(scb + j * 64);
        float d = 0.f;
#pragma unroll
        for (int l4 = 0; l4 < 16; l4++) {
            float4 w4 = bwp[l4];
            float4 x4 = bsp[l4];
            d += x4.x * w4.x + x4.y * w4.y + x4.z * w4.z + x4.w * w4.w;
        }
        d += body_b[j * NI + i];
        scb[512 + j * 32 + i] = gav[j] * d;
    }
    __syncthreads();
    if (t < 32) {
        float s = 0.f;
#pragma unroll
        for (int j = 0; j < 8; j++) s += scb[512 + j * 32 + t];
        g_cv[b * 32 + t] = s;
    }
}

// =============================================================================
// Kernel B: slot selector. grid = (16 b-tiles, 8 j, 2 k-halves), 256 threads.
// 8 chunks of 128 k per CTA. Thread tile 4k x 4b, FFMA2, float2 weight loads.
// smem: w_s 128*66 = 8448, lg 128*36 = 4608, bs 64*36 = 2304 -> 61440 B, occ 3
// =============================================================================
#define B_WS  0
#define B_LG  (128*66)                 // 8448
#define B_BS  (B_LG + 128*36)          // 13056
#define B_SMEM_FLOATS (B_BS + 64*36)   // 15360

extern "C" __global__ void __launch_bounds__(256, 3)
kB(const float* __restrict__ slot_w, const float* __restrict__ slot_b)
{
    extern __shared__ float sm[];
    float* w_s = sm + B_WS;
    float* lg  = sm + B_LG;
    float* bs  = sm + B_BS;

    const int t  = threadIdx.x;
    const int j  = blockIdx.y;
    const int b0 = blockIdx.x * 32;
    const int kh = blockIdx.z;

    const int q  = t & 7;                // phase b: b quad = q*4..q*4+3
    const int ko = t >> 3;               // phase b: k = ko*4+kk (0..127)
    const int cb = t & 31;               // phase c
    const int ls = (t >> 5) & 3;         // phase c (t<128)

    // stage best transposed: bs[l*36 + b]
    {
        int bb = t >> 3;                 // 0..31
        int l0 = (t & 7) * 8;            // 8 consecutive l
        const float4* gp = (const float4*)(&g_best[((size_t)j * NB + b0 + bb) * 64 + l0]);
        float4 v0 = gp[0], v1 = gp[1];
        bs[(l0+0)*36+bb]=v0.x; bs[(l0+1)*36+bb]=v0.y;
        bs[(l0+2)*36+bb]=v0.z; bs[(l0+3)*36+bb]=v0.w;
        bs[(l0+4)*36+bb]=v1.x; bs[(l0+5)*36+bb]=v1.y;
        bs[(l0+6)*36+bb]=v1.z; bs[(l0+7)*36+bb]=v1.w;
    }

    float accI[32];
#pragma unroll
    for (int i = 0; i < 32; i++) accI[i] = 0.f;

    const float* swj = slot_w + (size_t)j * (NK * NL) + (size_t)kh * 1024 * 64;
    const float* sbj = slot_b + j * NK + kh * 1024;

    for (int ch = 0; ch < 8; ch++) {
        __syncthreads();
        const float4* src = (const float4*)(swj + ch * 128 * 64);
#pragma unroll
        for (int qq = 0; qq < 8; qq++) {
            int f = t + 256 * qq;           // 0..2047
            int row = f >> 4, c4 = f & 15;
            float4 v = src[f];
            float* dst = w_s + row * 66 + c4 * 4;
            dst[0] = v.x; dst[1] = v.y; dst[2] = v.z; dst[3] = v.w;
        }
        __syncthreads();

        // ---- phase b: logits, 4k x 4b, f32x2 ----
        unsigned long long acc[4][2];
#pragma unroll
        for (int kk = 0; kk < 4; kk++) {
            float sv = sbj[ch * 128 + ko * 4 + kk];
            acc[kk][0] = pk2(sv, sv);
            acc[kk][1] = pk2(sv, sv);
        }
#pragma unroll 4
        for (int l = 0; l < 64; l += 2) {
            ulonglong2 p0 = *(const ulonglong2*)(bs + l * 36 + q * 4);
            ulonglong2 p1 = *(const ulonglong2*)(bs + (l + 1) * 36 + q * 4);
#pragma unroll
            for (int kk = 0; kk < 4; kk++) {
                float2 w2 = *(const float2*)(w_s + (ko * 4 + kk) * 66 + l);
                unsigned long long wa = pk2(w2.x, w2.x);
                unsigned long long wb = pk2(w2.y, w2.y);
                fma2(acc[kk][0], p0.x, wa); fma2(acc[kk][1], p0.y, wa);
                fma2(acc[kk][0], p1.x, wb); fma2(acc[kk][1], p1.y, wb);
            }
        }
#pragma unroll
        for (int kk = 0; kk < 4; kk++) {
            ulonglong2 o; o.x = acc[kk][0]; o.y = acc[kk][1];
            *(ulonglong2*)(lg + (ko * 4 + kk) * 36 + q * 4) = o;
        }
        __syncthreads();

        // ---- phase c: softmax over i for (b=cb, l_slot=ls), t<128 ----
        if (t < 128) {
            int l = kh * 32 + ch * 4 + ls;
            float lv[32];
            float m = -3.4e38f;
#pragma unroll
            for (int i = 0; i < 32; i++) {
                lv[i] = lg[(ls * 32 + i) * 36 + cb];
                m = fmaxf(m, lv[i]);
            }
            float Z = 0.f;
#pragma unroll
            for (int i = 0; i < 32; i++) {
                lv[i] = expf(lv[i] - m);
                Z += lv[i];
            }
            float s = bs[l * 36 + cb] / Z;
#pragma unroll
            for (int i = 0; i < 32; i++) accI[i] += lv[i] * s;
        }
    }
    __syncthreads();

    // reduce 4 l_slot partials per b (reuse w_s; pad 33)
    float* red2 = w_s;
    if (t < 128) {
#pragma unroll
        for (int i = 0; i < 32; i++) red2[(ls * 32 + cb) * 33 + i] = accI[i];
    }
    __syncthreads();
#pragma unroll
    for (int r = 0; r < 4; r++) {
        int e = t * 4 + r;               // 0..1023
        int bb = e >> 5, i = e & 31;
        float s = 0.f;
#pragma unroll
        for (int l4 = 0; l4 < 4; l4++) s += red2[(l4 * 32 + bb) * 33 + i];
        g_cvp[(((size_t)kh * NJ + j) * NB + b0 + bb) * 32 + i] = s;
    }
}

// =============================================================================
// Kernel C: cv_total = body + 16 slot partials; out = conf * (cv@W^T + b)
// =============================================================================
extern "C" __global__ void __launch_bounds__(128)
kC(const float* __restrict__ head_w, const float* __restrict__ head_b,
   float* __restrict__ out)
{
    __shared__ float cvt[32];
    __shared__ float hw[NO * 33];
    const int t = threadIdx.x;
    const int b = blockIdx.x;

#pragma unroll
    for (int r = 0; r < 32; r++) {
        int e = t + 128 * r;             // 0..4095
        int o = e >> 5, i = e & 31;
        hw[o * 33 + i] = head_w[e];
    }
    if (t < 32) {
        float v = g_cv[b * 32 + t];
#pragma unroll
        for (int p = 0; p < 16; p++)
            v += g_cvp[((size_t)p * NB + b) * 32 + t];
        cvt[t] = v;
    }
    __syncthreads();

    float d = head_b[t];
#pragma unroll
    for (int i = 0; i < 32; i++) d += cvt[i] * hw[t * 33 + i];
    out[b * NO + t] = g_conf[b] * d;
}

// =============================================================================
extern "C" void kernel_launch(void* const* d_in, const int* in_sizes, int n_in,
                              void* d_out, int out_size)
{
    const float* wm  = (const float*)d_in[0];
    const float* cst = (const float*)d_in[1];
    const float* gam = (const float*)d_in[2];
    const float* bw  = (const float*)d_in[3];
    const float* bb  = (const float*)d_in[4];
    const float* sw  = (const float*)d_in[5];
    const float* sb  = (const float*)d_in[6];
    const float* hwp = (const float*)d_in[7];
    const float* hbp = (const float*)d_in[8];
    float* out = (float*)d_out;

    cudaFuncSetAttribute(kA, cudaFuncAttributeMaxDynamicSharedMemorySize,
                         A_SMEM_FLOATS * 4);
    cudaFuncSetAttribute(kB, cudaFuncAttributeMaxDynamicSharedMemorySize,
                         B_SMEM_FLOATS * 4);

    kA<<<NB, 256, A_SMEM_FLOATS * 4>>>(wm, cst, gam, bw, bb);
    dim3 gb(16, 8, 2);
    kB<<<gb, 256, B_SMEM_FLOATS * 4>>>(sw, sb);
    kC<<<NB, 128>>>(hwp, hbp, out);
}

// round 12
// speedup vs baseline: 1.6633x; 1.0467x over previous
#include <cuda_runtime.h>
#include <math.h>

// Problem shapes (fixed)
#define NB 512
#define NW 1024
#define NL 64
#define NJ 8
#define NI 32
#define NO 128
#define NK 2048   // L*I

// ---------------- device scratch (no allocations allowed) -------------------
__device__ float g_best[NJ * NB * NL];       // best[j][b][l]        (1 MB)
__device__ float g_cv  [NB * NI];            // body contribution
__device__ float g_cvp [4 * NJ * NB * NI];   // slot partials [kq][j][b][i]
__device__ float g_conf[NB];                 // exp(-total_mq)

// ---------------- packed f32x2 helpers (Blackwell FFMA2) --------------------
static __device__ __forceinline__ unsigned long long pk2(float x, float y) {
    unsigned long long r;
    asm("mov.b64 %0, {%1,%2};" : "=l"(r) : "f"(x), "f"(y));
    return r;
}
static __device__ __forceinline__ void fma2(unsigned long long& d,
                                            unsigned long long a,
                                            unsigned long long b) {
    asm("fma.rn.f32x2 %0, %1, %2, %0;" : "+l"(d) : "l"(a), "l"(b));
}
static __device__ __forceinline__ float2 up2(unsigned long long v) {
    float2 r;
    asm("mov.b64 {%0,%1}, %2;" : "=f"(r.x), "=f"(r.y) : "l"(v));
    return r;
}

// =============================================================================
// Kernel A: per-b fully fused, single wm staging, streaming softmax with a
// fixed exp-offset C_j = min(scores of chunk 0).
// grid = 512 CTAs (one per b), 256 threads, 8 chunks of 128 w.
// Score phase: thread owns (w = t&127) x (j in 4*(t>>7)..+3): 9 instr / 4 scores
// Best phase:  warp owns 16-w slice, all 8 j as packed (j,j+1) pairs.
// smem ~41.8 KB -> single wave at 512 CTAs.
// =============================================================================
#define CW     128
#define A_COEF 0
#define A_TILE 1024
#define A_SCB  (A_TILE + 128*65)      // 9344
#define A_AS   (A_SCB + 1024)         // 10368
#define A_GAV  (A_AS + 8)
#define A_CS   (A_GAV + 8)
#define A_RZ   (A_CS + 8)
#define A_MQS  (A_RZ + 8)
#define A_ZW   (A_MQS + 8)            // 8 warps x 4
#define A_QW   (A_ZW + 32)
#define A_SMEM_FLOATS (A_QW + 32)     // 10472

extern "C" __global__ void __launch_bounds__(256, 4)
kA(const float* __restrict__ wm, const float* __restrict__ constants,
   const float* __restrict__ gammas, const float* __restrict__ body_w,
   const float* __restrict__ body_b)
{
    extern __shared__ float sm[];
    unsigned long long* coefT = (unsigned long long*)(sm + A_COEF); // [l*8+j]
    float* tile = sm + A_TILE;
    float* scb  = sm + A_SCB;
    float* As   = sm + A_AS;
    float* gav  = sm + A_GAV;
    float* Cs   = sm + A_CS;
    float* rz   = sm + A_RZ;
    float* mqs  = sm + A_MQS;
    float* zw   = sm + A_ZW;
    float* qw   = sm + A_QW;

    const int t    = threadIdx.x;
    const int b    = blockIdx.x;
    const int lane = t & 31;
    const int wid  = t >> 5;
    const int wp   = t & 127;         // score phase: the one w this thread owns
    const int jh   = t >> 7;          // score phase: j in {4jh..4jh+3}

    // ---- Phase 0: coefficients (scratch in tile) ----
    for (int e = t; e < NJ * NL; e += 256) {
        int j = e >> 6, l = e & 63;
        float g = gammas[e];
        g = fminf(fmaxf(g, 0.f), 1.f);
        float w1 = 1.f - g;
        float c  = constants[e];
        coefT[l * 8 + j] = pk2(-2.f * w1 * c, w1);
        tile[e]       = w1 * c * c;
        tile[512 + e] = g;
    }
    __syncthreads();
    if (t < 8) {
        float a = 0.f, s = 0.f;
        for (int l = 0; l < NL; l++) { a += tile[t*64 + l]; s += tile[512 + t*64 + l]; }
        As[t]  = a;
        gav[t] = s * (1.f / 64.f);
    }
    __syncthreads();

    float Areg[4];
#pragma unroll
    for (int k = 0; k < 4; k++) Areg[k] = As[4 * jh + k];
    const ulonglong2* cT = (const ulonglong2*)coefT;   // [l*4 + 2jh (+1)]
    const float* wmb = wm + (size_t)b * (NW * NL);

    unsigned long long accP[2][4];        // best accum: [x-half][(j,j+1) pair]
#pragma unroll
    for (int h = 0; h < 2; h++)
#pragma unroll
        for (int p = 0; p < 4; p++) accP[h][p] = pk2(0.f, 0.f);
    float zp[4] = {0.f, 0.f, 0.f, 0.f};
    float qp[4] = {0.f, 0.f, 0.f, 0.f};
    float Cr[4] = {0.f, 0.f, 0.f, 0.f};   // exp offsets (set @ ch0)

    for (int ch = 0; ch < 8; ch++) {
        __syncthreads();
        // ---- stage 128-w chunk ----
        const float4* src = (const float4*)(wmb + ch * CW * 64);
#pragma unroll
        for (int qq = 0; qq < 8; qq++) {
            int f = t + 256 * qq;            // 0..2047 float4s
            int row = f >> 4, c4 = f & 15;
            float4 v = src[f];
            float* dst = tile + row * 65 + c4 * 4;
            dst[0] = v.x; dst[1] = v.y; dst[2] = v.z; dst[3] = v.w;
        }
        __syncthreads();

        // ---- scores for w=wp, j=4jh..4jh+3: 9 instr per l ----
        unsigned long long s0 = pk2(Areg[0], 0.f);
        unsigned long long s1 = pk2(Areg[1], 0.f);
        unsigned long long s2 = pk2(Areg[2], 0.f);
        unsigned long long s3 = pk2(Areg[3], 0.f);
        const float* r0 = tile + wp * 65;
#pragma unroll 16
        for (int l = 0; l < 64; l++) {
            float x = r0[l];
            unsigned long long a0 = pk2(x, x * x);
            ulonglong2 ccA = cT[l * 4 + 2 * jh];
            ulonglong2 ccB = cT[l * 4 + 2 * jh + 1];
            fma2(s0, a0, ccA.x); fma2(s1, a0, ccA.y);
            fma2(s2, a0, ccB.x); fma2(s3, a0, ccB.y);
        }
        float sv[4];
        { float2 p = up2(s0); sv[0] = p.x + p.y; }
        { float2 p = up2(s1); sv[1] = p.x + p.y; }
        { float2 p = up2(s2); sv[2] = p.x + p.y; }
        { float2 p = up2(s3); sv[3] = p.x + p.y; }

        if (ch == 0) {
            // establish exp offsets C_j = min over chunk-0 scores
            *(float4*)(scb + wp * 8 + 4 * jh) = make_float4(sv[0], sv[1], sv[2], sv[3]);
            __syncthreads();
            float mn = 3.4e38f;                      // warp wid handles j=wid
#pragma unroll
            for (int r = 0; r < 4; r++)
                mn = fminf(mn, scb[(lane + 32 * r) * 8 + wid]);
#pragma unroll
            for (int o = 16; o; o >>= 1)
                mn = fminf(mn, __shfl_xor_sync(0xffffffffu, mn, o));
            if (lane == 0) Cs[wid] = mn;
            __syncthreads();
#pragma unroll
            for (int k = 0; k < 4; k++) Cr[k] = Cs[4 * jh + k];
        }

        float e[4];
#pragma unroll
        for (int k = 0; k < 4; k++) {
            e[k] = __expf(Cr[k] - sv[k]);
            zp[k] += e[k];
            qp[k] += e[k] * sv[k];
        }
        *(float4*)(scb + wp * 8 + 4 * jh) = make_float4(e[0], e[1], e[2], e[3]);
        __syncthreads();

        // ---- best accumulate: warp owns 16-w slice, j-pairs packed ----
        const int w0 = wid * 16;
        const ulonglong2* arow = (const ulonglong2*)scb;
#pragma unroll 8
        for (int i = 0; i < 16; i++) {
            int wl = w0 + i;
            ulonglong2 A0 = arow[wl * 2];        // (j0,j1),(j2,j3)
            ulonglong2 A1 = arow[wl * 2 + 1];    // (j4,j5),(j6,j7)
            float x0 = tile[wl * 65 + lane];
            float x1 = tile[wl * 65 + 32 + lane];
            unsigned long long xx0 = pk2(x0, x0);
            unsigned long long xx1 = pk2(x1, x1);
            fma2(accP[0][0], A0.x, xx0); fma2(accP[0][1], A0.y, xx0);
            fma2(accP[0][2], A1.x, xx0); fma2(accP[0][3], A1.y, xx0);
            fma2(accP[1][0], A0.x, xx1); fma2(accP[1][1], A0.y, xx1);
            fma2(accP[1][2], A1.x, xx1); fma2(accP[1][3], A1.y, xx1);
        }
    }

    // ---- Z/MQ reduction: warp-reduce, then cross-warp within jh group ----
#pragma unroll
    for (int o = 16; o; o >>= 1)
#pragma unroll
        for (int k = 0; k < 4; k++) {
            zp[k] += __shfl_xor_sync(0xffffffffu, zp[k], o);
            qp[k] += __shfl_xor_sync(0xffffffffu, qp[k], o);
        }
    __syncthreads();                       // chunk loop done; reuse tile
    if (lane == 0) {
#pragma unroll
        for (int k = 0; k < 4; k++) { zw[wid * 4 + k] = zp[k]; qw[wid * 4 + k] = qp[k]; }
    }
    // dump best partials (warp-sliced) into tile
    float* red = tile;
#pragma unroll
    for (int p = 0; p < 4; p++) {
        float2 v0 = up2(accP[0][p]);
        float2 v1 = up2(accP[1][p]);
        red[(wid * 8 + 2 * p    ) * 64 + lane]      = v0.x;
        red[(wid * 8 + 2 * p + 1) * 64 + lane]      = v0.y;
        red[(wid * 8 + 2 * p    ) * 64 + 32 + lane] = v1.x;
        red[(wid * 8 + 2 * p + 1) * 64 + 32 + lane] = v1.y;
    }
    __syncthreads();
    if (t < 8) {                            // j = t; warps 4*(j>>2)..+3 hold it
        int h = t >> 2, k = t & 3;
        float Z = 0.f, Q = 0.f;
#pragma unroll
        for (int u = 0; u < 4; u++) {
            Z += zw[(4 * h + u) * 4 + k];
            Q += qw[(4 * h + u) * 4 + k];
        }
        rz[t]  = 1.f / Z;
        mqs[t] = Q / Z;
    }
    __syncthreads();
    if (t == 0) {
        float tm = 0.f;
#pragma unroll
        for (int j = 0; j < 8; j++) tm += mqs[j];
        g_conf[b] = expf(-tm);
    }
    // ---- best finalize (scb reused as best buffer) ----
    {
        const int j = t >> 5;
        float b0 = 0.f, b1 = 0.f;
#pragma unroll
        for (int w8 = 0; w8 < 8; w8++) {
            b0 += red[(w8 * 8 + j) * 64 + lane];
            b1 += red[(w8 * 8 + j) * 64 + 32 + lane];
        }
        float r = rz[j];
        b0 *= r; b1 *= r;
        scb[j * 64 + lane]      = b0;
        scb[j * 64 + 32 + lane] = b1;
        g_best[((size_t)j * NB + b) * 64 + lane]      = b0;
        g_best[((size_t)j * NB + b) * 64 + 32 + lane] = b1;
    }
    __syncthreads();

    // ---- body path ----
    {
        const int j = t >> 5, i = t & 31;
        const float4* bwp = (const float4*)(body_w + (j * NI + i) * NL);
        const float4* bsp = (const float4*)(scb + j * 64);
        float d = 0.f;
#pragma unroll
        for (int l4 = 0; l4 < 16; l4++) {
            float4 w4 = bwp[l4];
            float4 x4 = bsp[l4];
            d += x4.x * w4.x + x4.y * w4.y + x4.z * w4.z + x4.w * w4.w;
        }
        d += body_b[j * NI + i];
        scb[512 + j * 32 + i] = gav[j] * d;
    }
    __syncthreads();
    if (t < 32) {
        float s = 0.f;
#pragma unroll
        for (int j = 0; j < 8; j++) s += scb[512 + j * 32 + t];
        g_cv[b * 32 + t] = s;
    }
}

// =============================================================================
// Kernel B: slot selector. grid = (16 b-tiles, 8 j, 4 k-quarters), 256 thr.
// 4 chunks of 128 k per CTA. Thread tile 4k x 4b, FFMA2, float2 weight loads.
// smem: w_s 128*66, lg 128*36, bs 64*36 -> 61.4 KB, occ 3, 512 CTAs.
// =============================================================================
#define B_WS  0
#define B_LG  (128*66)                 // 8448
#define B_BS  (B_LG + 128*36)          // 13056
#define B_SMEM_FLOATS (B_BS + 64*36)   // 15360

extern "C" __global__ void __launch_bounds__(256, 3)
kB(const float* __restrict__ slot_w, const float* __restrict__ slot_b)
{
    extern __shared__ float sm[];
    float* w_s = sm + B_WS;
    float* lg  = sm + B_LG;
    float* bs  = sm + B_BS;

    const int t  = threadIdx.x;
    const int j  = blockIdx.y;
    const int b0 = blockIdx.x * 32;
    const int kq = blockIdx.z;           // k-quarter (512 k each)

    const int q  = t & 7;                // phase b: b quad = q*4..q*4+3
    const int ko = t >> 3;               // phase b: k = ko*4+kk (0..127)
    const int cb = t & 31;               // phase c
    const int ls = (t >> 5) & 3;         // phase c (t<128)

    // stage best transposed: bs[l*36 + b]
    {
        int bb = t >> 3;                 // 0..31
        int l0 = (t & 7) * 8;            // 8 consecutive l
        const float4* gp = (const float4*)(&g_best[((size_t)j * NB + b0 + bb) * 64 + l0]);
        float4 v0 = gp[0], v1 = gp[1];
        bs[(l0+0)*36+bb]=v0.x; bs[(l0+1)*36+bb]=v0.y;
        bs[(l0+2)*36+bb]=v0.z; bs[(l0+3)*36+bb]=v0.w;
        bs[(l0+4)*36+bb]=v1.x; bs[(l0+5)*36+bb]=v1.y;
        bs[(l0+6)*36+bb]=v1.z; bs[(l0+7)*36+bb]=v1.w;
    }

    float accI[32];
#pragma unroll
    for (int i = 0; i < 32; i++) accI[i] = 0.f;

    const float* swj = slot_w + (size_t)j * (NK * NL) + (size_t)kq * 512 * 64;
    const float* sbj = slot_b + j * NK + kq * 512;

    for (int ch = 0; ch < 4; ch++) {
        __syncthreads();
        const float4* src = (const float4*)(swj + ch * 128 * 64);
#pragma unroll
        for (int qq = 0; qq < 8; qq++) {
            int f = t + 256 * qq;           // 0..2047
            int row = f >> 4, c4 = f & 15;
            float4 v = src[f];
            float* dst = w_s + row * 66 + c4 * 4;
            dst[0] = v.x; dst[1] = v.y; dst[2] = v.z; dst[3] = v.w;
        }
        __syncthreads();

        // ---- phase b: logits, 4k x 4b, f32x2 ----
        unsigned long long acc[4][2];
#pragma unroll
        for (int kk = 0; kk < 4; kk++) {
            float svv = sbj[ch * 128 + ko * 4 + kk];
            acc[kk][0] = pk2(svv, svv);
            acc[kk][1] = pk2(svv, svv);
        }
#pragma unroll 4
        for (int l = 0; l < 64; l += 2) {
            ulonglong2 p0 = *(const ulonglong2*)(bs + l * 36 + q * 4);
            ulonglong2 p1 = *(const ulonglong2*)(bs + (l + 1) * 36 + q * 4);
#pragma unroll
            for (int kk = 0; kk < 4; kk++) {
                float2 w2 = *(const float2*)(w_s + (ko * 4 + kk) * 66 + l);
                unsigned long long wa = pk2(w2.x, w2.x);
                unsigned long long wb = pk2(w2.y, w2.y);
                fma2(acc[kk][0], p0.x, wa); fma2(acc[kk][1], p0.y, wa);
                fma2(acc[kk][0], p1.x, wb); fma2(acc[kk][1], p1.y, wb);
            }
        }
#pragma unroll
        for (int kk = 0; kk < 4; kk++) {
            ulonglong2 o; o.x = acc[kk][0]; o.y = acc[kk][1];
            *(ulonglong2*)(lg + (ko * 4 + kk) * 36 + q * 4) = o;
        }
        __syncthreads();

        // ---- phase c: softmax over i for (b=cb, l_slot=ls), t<128 ----
        if (t < 128) {
            int l = kq * 16 + ch * 4 + ls;
            float lv[32];
            float m = -3.4e38f;
#pragma unroll
            for (int i = 0; i < 32; i++) {
                lv[i] = lg[(ls * 32 + i) * 36 + cb];
                m = fmaxf(m, lv[i]);
            }
            float Z = 0.f;
#pragma unroll
            for (int i = 0; i < 32; i++) {
                lv[i] = __expf(lv[i] - m);
                Z += lv[i];
            }
            float s = bs[l * 36 + cb] / Z;
#pragma unroll
            for (int i = 0; i < 32; i++) accI[i] += lv[i] * s;
        }
    }
    __syncthreads();

    // reduce 4 l_slot partials per b (reuse w_s; pad 33)
    float* red2 = w_s;
    if (t < 128) {
#pragma unroll
        for (int i = 0; i < 32; i++) red2[(ls * 32 + cb) * 33 + i] = accI[i];
    }
    __syncthreads();
#pragma unroll
    for (int r = 0; r < 4; r++) {
        int e = t * 4 + r;               // 0..1023
        int bb = e >> 5, i = e & 31;
        float s = 0.f;
#pragma unroll
        for (int l4 = 0; l4 < 4; l4++) s += red2[(l4 * 32 + bb) * 33 + i];
        g_cvp[(((size_t)kq * NJ + j) * NB + b0 + bb) * 32 + i] = s;
    }
}

// =============================================================================
// Kernel C: cv_total = body + 32 slot partials; out = conf * (cv@W^T + b)
// =============================================================================
extern "C" __global__ void __launch_bounds__(128)
kC(const float* __restrict__ head_w, const float* __restrict__ head_b,
   float* __restrict__ out)
{
    __shared__ float cvt[32];
    __shared__ float hw[NO * 33];
    const int t = threadIdx.x;
    const int b = blockIdx.x;

#pragma unroll
    for (int r = 0; r < 32; r++) {
        int e = t + 128 * r;             // 0..4095
        int o = e >> 5, i = e & 31;
        hw[o * 33 + i] = head_w[e];
    }
    if (t < 32) {
        float v = g_cv[b * 32 + t];
#pragma unroll
        for (int p = 0; p < 32; p++)
            v += g_cvp[((size_t)p * NB + b) * 32 + t];
        cvt[t] = v;
    }
    __syncthreads();

    float d = head_b[t];
#pragma unroll
    for (int i = 0; i < 32; i++) d += cvt[i] * hw[t * 33 + i];
    out[b * NO + t] = g_conf[b] * d;
}

// =============================================================================
extern "C" void kernel_launch(void* const* d_in, const int* in_sizes, int n_in,
                              void* d_out, int out_size)
{
    const float* wm  = (const float*)d_in[0];
    const float* cst = (const float*)d_in[1];
    const float* gam = (const float*)d_in[2];
    const float* bw  = (const float*)d_in[3];
    const float* bb  = (const float*)d_in[4];
    const float* sw  = (const float*)d_in[5];
    const float* sb  = (const float*)d_in[6];
    const float* hwp = (const float*)d_in[7];
    const float* hbp = (const float*)d_in[8];
    float* out = (float*)d_out;

    cudaFuncSetAttribute(kA, cudaFuncAttributeMaxDynamicSharedMemorySize,
                         A_SMEM_FLOATS * 4);
    cudaFuncSetAttribute(kB, cudaFuncAttributeMaxDynamicSharedMemorySize,
                         B_SMEM_FLOATS * 4);

    kA<<<NB, 256, A_SMEM_FLOATS * 4>>>(wm, cst, gam, bw, bb);
    dim3 gb(16, 8, 4);
    kB<<<gb, 256, B_SMEM_FLOATS * 4>>>(sw, sb);
    kC<<<NB, 128>>>(hwp, hbp, out);
}

// round 13
// speedup vs baseline: 1.7728x; 1.0659x over previous
#include <cuda_runtime.h>
#include <math.h>

// Problem shapes (fixed)
#define NB 512
#define NW 1024
#define NL 64
#define NJ 8
#define NI 32
#define NO 128
#define NK 2048   // L*I

// ---------------- device scratch (no allocations allowed) -------------------
__device__ float g_best[NJ * NB * NL];       // best[j][b][l]        (1 MB)
__device__ float g_cv  [NB * NI];            // body contribution
__device__ float g_cvp [4 * NJ * NB * NI];   // slot partials [kq][j][b][i]
__device__ float g_conf[NB];                 // exp(-total_mq)

// ---------------- packed f32x2 helpers (Blackwell FFMA2) --------------------
static __device__ __forceinline__ unsigned long long pk2(float x, float y) {
    unsigned long long r;
    asm("mov.b64 %0, {%1,%2};" : "=l"(r) : "f"(x), "f"(y));
    return r;
}
static __device__ __forceinline__ void fma2(unsigned long long& d,
                                            unsigned long long a,
                                            unsigned long long b) {
    asm("fma.rn.f32x2 %0, %1, %2, %0;" : "+l"(d) : "l"(a), "l"(b));
}
static __device__ __forceinline__ float2 up2(unsigned long long v) {
    float2 r;
    asm("mov.b64 {%0,%1}, %2;" : "=f"(r.x), "=f"(r.y) : "l"(v));
    return r;
}

// =============================================================================
// Kernel A: per-b fully fused, 128 THREADS per CTA, 8 chunks of 128 w.
// Score tile per thread: W=2 (wp, wp+64) x J=4 (jh*4..+3) -> 0.5 wf/FFMA2.
// Best phase: warp (of 4) owns 32-w slice, all 8 j as packed (j,j+1) pairs.
// smem ~41.9 KB -> 5 CTAs/SM, single wave at 512 CTAs.
// =============================================================================
#define CW     128
#define A_COEF 0
#define A_TILE 1024
#define A_SCB  (A_TILE + 128*65)      // 9344
#define A_AS   (A_SCB + 1024)         // 10368
#define A_GAV  (A_AS + 8)
#define A_CS   (A_GAV + 8)
#define A_RZ   (A_CS + 8)
#define A_MQS  (A_RZ + 8)
#define A_ZW   (A_MQS + 8)            // 4 warps x 4
#define A_QW   (A_ZW + 16)
#define A_SMEM_FLOATS (A_QW + 16)     // 10456

extern "C" __global__ void __launch_bounds__(128, 5)
kA(const float* __restrict__ wm, const float* __restrict__ constants,
   const float* __restrict__ gammas, const float* __restrict__ body_w,
   const float* __restrict__ body_b)
{
    extern __shared__ float sm[];
    unsigned long long* coefT = (unsigned long long*)(sm + A_COEF); // [l*8+j]
    float* tile = sm + A_TILE;
    float* scb  = sm + A_SCB;
    float* As   = sm + A_AS;
    float* gav  = sm + A_GAV;
    float* Cs   = sm + A_CS;
    float* rz   = sm + A_RZ;
    float* mqs  = sm + A_MQS;
    float* zw   = sm + A_ZW;
    float* qw   = sm + A_QW;

    const int t    = threadIdx.x;
    const int b    = blockIdx.x;
    const int lane = t & 31;
    const int wid  = t >> 5;          // 0..3
    const int wp   = t & 63;          // score: w in {wp, wp+64}
    const int jh   = t >> 6;          // score: j in {4jh..4jh+3}

    // ---- Phase 0: coefficients (scratch in tile) ----
    for (int e = t; e < NJ * NL; e += 128) {
        int j = e >> 6, l = e & 63;
        float g = gammas[e];
        g = fminf(fmaxf(g, 0.f), 1.f);
        float w1 = 1.f - g;
        float c  = constants[e];
        coefT[l * 8 + j] = pk2(-2.f * w1 * c, w1);
        tile[e]       = w1 * c * c;
        tile[512 + e] = g;
    }
    __syncthreads();
    if (t < 8) {
        float a = 0.f, s = 0.f;
        for (int l = 0; l < NL; l++) { a += tile[t*64 + l]; s += tile[512 + t*64 + l]; }
        As[t]  = a;
        gav[t] = s * (1.f / 64.f);
    }
    __syncthreads();

    float Areg[4];
#pragma unroll
    for (int k = 0; k < 4; k++) Areg[k] = As[4 * jh + k];
    const ulonglong2* cT = (const ulonglong2*)coefT;   // [l*4 + 2jh (+1)]
    const float* wmb = wm + (size_t)b * (NW * NL);

    unsigned long long accP[2][4];        // best accum: [x-half][(j,j+1) pair]
#pragma unroll
    for (int h = 0; h < 2; h++)
#pragma unroll
        for (int p = 0; p < 4; p++) accP[h][p] = pk2(0.f, 0.f);
    float zp[4] = {0.f, 0.f, 0.f, 0.f};
    float qp[4] = {0.f, 0.f, 0.f, 0.f};
    float Cr[4] = {0.f, 0.f, 0.f, 0.f};   // exp offsets (set @ ch0)

    for (int ch = 0; ch < 8; ch++) {
        __syncthreads();
        // ---- stage 128-w chunk (128 threads, 16 float4 each) ----
        const float4* src = (const float4*)(wmb + ch * CW * 64);
#pragma unroll
        for (int qq = 0; qq < 16; qq++) {
            int f = t + 128 * qq;            // 0..2047 float4s
            int row = f >> 4, c4 = f & 15;
            float4 v = src[f];
            float* dst = tile + row * 65 + c4 * 4;
            dst[0] = v.x; dst[1] = v.y; dst[2] = v.z; dst[3] = v.w;
        }
        __syncthreads();

        // ---- scores: w in {wp, wp+64}, j = 4jh..4jh+3 ----
        unsigned long long s00 = pk2(Areg[0], 0.f);
        unsigned long long s01 = pk2(Areg[1], 0.f);
        unsigned long long s02 = pk2(Areg[2], 0.f);
        unsigned long long s03 = pk2(Areg[3], 0.f);
        unsigned long long s10 = s00, s11 = s01, s12 = s02, s13 = s03;
        const float* r0 = tile + wp * 65;
        const float* r1 = tile + (wp + 64) * 65;
#pragma unroll 16
        for (int l = 0; l < 64; l++) {
            float x0 = r0[l], x1 = r1[l];
            unsigned long long a0 = pk2(x0, x0 * x0);
            unsigned long long a1 = pk2(x1, x1 * x1);
            ulonglong2 ccA = cT[l * 4 + 2 * jh];
            ulonglong2 ccB = cT[l * 4 + 2 * jh + 1];
            fma2(s00, a0, ccA.x); fma2(s01, a0, ccA.y);
            fma2(s02, a0, ccB.x); fma2(s03, a0, ccB.y);
            fma2(s10, a1, ccA.x); fma2(s11, a1, ccA.y);
            fma2(s12, a1, ccB.x); fma2(s13, a1, ccB.y);
        }
        float sv0[4], sv1[4];
        { float2 p = up2(s00); sv0[0] = p.x + p.y; }
        { float2 p = up2(s01); sv0[1] = p.x + p.y; }
        { float2 p = up2(s02); sv0[2] = p.x + p.y; }
        { float2 p = up2(s03); sv0[3] = p.x + p.y; }
        { float2 p = up2(s10); sv1[0] = p.x + p.y; }
        { float2 p = up2(s11); sv1[1] = p.x + p.y; }
        { float2 p = up2(s12); sv1[2] = p.x + p.y; }
        { float2 p = up2(s13); sv1[3] = p.x + p.y; }

        if (ch == 0) {
            // establish exp offsets C_j = min over chunk-0 scores
            *(float4*)(scb + wp * 8 + 4 * jh)        = make_float4(sv0[0], sv0[1], sv0[2], sv0[3]);
            *(float4*)(scb + (wp + 64) * 8 + 4 * jh) = make_float4(sv1[0], sv1[1], sv1[2], sv1[3]);
            __syncthreads();
#pragma unroll
            for (int k = 0; k < 2; k++) {          // warp wid handles j=2wid+k
                int j = 2 * wid + k;
                float mn = 3.4e38f;
#pragma unroll
                for (int r = 0; r < 4; r++)
                    mn = fminf(mn, scb[(lane + 32 * r) * 8 + j]);
#pragma unroll
                for (int o = 16; o; o >>= 1)
                    mn = fminf(mn, __shfl_xor_sync(0xffffffffu, mn, o));
                if (lane == 0) Cs[j] = mn;
            }
            __syncthreads();
#pragma unroll
            for (int k = 0; k < 4; k++) Cr[k] = Cs[4 * jh + k];
        }

        float e0[4], e1[4];
#pragma unroll
        for (int k = 0; k < 4; k++) {
            e0[k] = __expf(Cr[k] - sv0[k]);
            e1[k] = __expf(Cr[k] - sv1[k]);
            zp[k] += e0[k] + e1[k];
            qp[k] += e0[k] * sv0[k] + e1[k] * sv1[k];
        }
        *(float4*)(scb + wp * 8 + 4 * jh)        = make_float4(e0[0], e0[1], e0[2], e0[3]);
        *(float4*)(scb + (wp + 64) * 8 + 4 * jh) = make_float4(e1[0], e1[1], e1[2], e1[3]);
        __syncthreads();

        // ---- best accumulate: warp owns 32-w slice, j-pairs packed ----
        const int w0 = wid * 32;
        const ulonglong2* arow = (const ulonglong2*)scb;
#pragma unroll 8
        for (int i = 0; i < 32; i++) {
            int wl = w0 + i;
            ulonglong2 A0 = arow[wl * 2];        // (j0,j1),(j2,j3)
            ulonglong2 A1 = arow[wl * 2 + 1];    // (j4,j5),(j6,j7)
            float x0 = tile[wl * 65 + lane];
            float x1 = tile[wl * 65 + 32 + lane];
            unsigned long long xx0 = pk2(x0, x0);
            unsigned long long xx1 = pk2(x1, x1);
            fma2(accP[0][0], A0.x, xx0); fma2(accP[0][1], A0.y, xx0);
            fma2(accP[0][2], A1.x, xx0); fma2(accP[0][3], A1.y, xx0);
            fma2(accP[1][0], A0.x, xx1); fma2(accP[1][1], A0.y, xx1);
            fma2(accP[1][2], A1.x, xx1); fma2(accP[1][3], A1.y, xx1);
        }
    }

    // ---- Z/MQ reduction ----
#pragma unroll
    for (int o = 16; o; o >>= 1)
#pragma unroll
        for (int k = 0; k < 4; k++) {
            zp[k] += __shfl_xor_sync(0xffffffffu, zp[k], o);
            qp[k] += __shfl_xor_sync(0xffffffffu, qp[k], o);
        }
    __syncthreads();                       // chunk loop done; reuse tile
    if (lane == 0) {
#pragma unroll
        for (int k = 0; k < 4; k++) { zw[wid * 4 + k] = zp[k]; qw[wid * 4 + k] = qp[k]; }
    }
    // dump best partials (warp-sliced) into tile
    float* red = tile;
#pragma unroll
    for (int p = 0; p < 4; p++) {
        float2 v0 = up2(accP[0][p]);
        float2 v1 = up2(accP[1][p]);
        red[(wid * 8 + 2 * p    ) * 64 + lane]      = v0.x;
        red[(wid * 8 + 2 * p + 1) * 64 + lane]      = v0.y;
        red[(wid * 8 + 2 * p    ) * 64 + 32 + lane] = v1.x;
        red[(wid * 8 + 2 * p + 1) * 64 + 32 + lane] = v1.y;
    }
    __syncthreads();
    if (t < 8) {                   // j = t; warps {2h,2h+1} hold it (h=j>>2)
        int h = t >> 2, k = t & 3;
        float Z = zw[(2 * h) * 4 + k] + zw[(2 * h + 1) * 4 + k];
        float Q = qw[(2 * h) * 4 + k] + qw[(2 * h + 1) * 4 + k];
        rz[t]  = 1.f / Z;
        mqs[t] = Q / Z;
    }
    __syncthreads();
    if (t == 0) {
        float tm = 0.f;
#pragma unroll
        for (int j = 0; j < 8; j++) tm += mqs[j];
        g_conf[b] = expf(-tm);
    }
    // ---- best finalize (scb reused as best buffer) ----
#pragma unroll
    for (int rep = 0; rep < 2; rep++) {
        const int j = wid + 4 * rep;
        float b0 = 0.f, b1 = 0.f;
#pragma unroll
        for (int w4 = 0; w4 < 4; w4++) {
            b0 += red[(w4 * 8 + j) * 64 + lane];
            b1 += red[(w4 * 8 + j) * 64 + 32 + lane];
        }
        float r = rz[j];
        b0 *= r; b1 *= r;
        scb[j * 64 + lane]      = b0;
        scb[j * 64 + 32 + lane] = b1;
        g_best[((size_t)j * NB + b) * 64 + lane]      = b0;
        g_best[((size_t)j * NB + b) * 64 + 32 + lane] = b1;
    }
    __syncthreads();

    // ---- body path: 256 (j,i) items over 128 threads ----
    {
        float outv[2];
#pragma unroll
        for (int rep = 0; rep < 2; rep++) {
            int idx = t + 128 * rep;
            int j = idx >> 5, i = idx & 31;
            const float4* bwp = (const float4*)(body_w + (j * NI + i) * NL);
            const float4* bsp = (const float4*)(scb + j * 64);
            float d = 0.f;
#pragma unroll
            for (int l4 = 0; l4 < 16; l4++) {
                float4 w4 = bwp[l4];
                float4 x4 = bsp[l4];
                d += x4.x * w4.x + x4.y * w4.y + x4.z * w4.z + x4.w * w4.w;
            }
            d += body_b[j * NI + i];
            outv[rep] = gav[j] * d;
        }
        __syncthreads();
#pragma unroll
        for (int rep = 0; rep < 2; rep++) {
            int idx = t + 128 * rep;
            tile[idx] = outv[rep];            // tile reused as [j*32+i]
        }
    }
    __syncthreads();
    if (t < 32) {
        float s = 0.f;
#pragma unroll
        for (int j = 0; j < 8; j++) s += tile[j * 32 + t];
        g_cv[b * 32 + t] = s;
    }
}

// =============================================================================
// Kernel B: slot selector. grid = (16 b-tiles, 8 j, 4 k-quarters), 256 thr.
// 4 chunks of 128 k per CTA. Phase b: 4k x 4b FFMA2. Phase c: ALL 256 threads
// (thread pair (t, t^128) splits the 32-i softmax, exchanging via smem).
// =============================================================================
#define B_WS  0
#define B_LG  (128*66)                 // 8448
#define B_BS  (B_LG + 128*36)          // 13056
#define B_PM  (B_BS + 64*36)           // 15360
#define B_SMEM_FLOATS (B_PM + 256)     // 15616 floats = 62464 B, occ 3

extern "C" __global__ void __launch_bounds__(256, 3)
kB(const float* __restrict__ slot_w, const float* __restrict__ slot_b)
{
    extern __shared__ float sm[];
    float* w_s = sm + B_WS;
    float* lg  = sm + B_LG;
    float* bs  = sm + B_BS;
    float* pm  = sm + B_PM;

    const int t  = threadIdx.x;
    const int j  = blockIdx.y;
    const int b0 = blockIdx.x * 32;
    const int kq = blockIdx.z;           // k-quarter (512 k each)

    const int q  = t & 7;                // phase b: b quad = q*4..q*4+3
    const int ko = t >> 3;               // phase b: k = ko*4+kk (0..127)
    const int cb = t & 31;               // phase c: b
    const int ls = (t >> 5) & 3;         // phase c: l_slot
    const int ih = t >> 7;               // phase c: i half (0/1)

    // stage best transposed: bs[l*36 + b]
    {
        int bb = t >> 3;                 // 0..31
        int l0 = (t & 7) * 8;            // 8 consecutive l
        const float4* gp = (const float4*)(&g_best[((size_t)j * NB + b0 + bb) * 64 + l0]);
        float4 v0 = gp[0], v1 = gp[1];
        bs[(l0+0)*36+bb]=v0.x; bs[(l0+1)*36+bb]=v0.y;
        bs[(l0+2)*36+bb]=v0.z; bs[(l0+3)*36+bb]=v0.w;
        bs[(l0+4)*36+bb]=v1.x; bs[(l0+5)*36+bb]=v1.y;
        bs[(l0+6)*36+bb]=v1.z; bs[(l0+7)*36+bb]=v1.w;
    }

    float accI[16];
#pragma unroll
    for (int i = 0; i < 16; i++) accI[i] = 0.f;

    const float* swj = slot_w + (size_t)j * (NK * NL) + (size_t)kq * 512 * 64;
    const float* sbj = slot_b + j * NK + kq * 512;

    for (int ch = 0; ch < 4; ch++) {
        __syncthreads();
        const float4* src = (const float4*)(swj + ch * 128 * 64);
#pragma unroll
        for (int qq = 0; qq < 8; qq++) {
            int f = t + 256 * qq;           // 0..2047
            int row = f >> 4, c4 = f & 15;
            float4 v = src[f];
            float* dst = w_s + row * 66 + c4 * 4;
            dst[0] = v.x; dst[1] = v.y; dst[2] = v.z; dst[3] = v.w;
        }
        __syncthreads();

        // ---- phase b: logits, 4k x 4b, f32x2 ----
        unsigned long long acc[4][2];
#pragma unroll
        for (int kk = 0; kk < 4; kk++) {
            float svv = sbj[ch * 128 + ko * 4 + kk];
            acc[kk][0] = pk2(svv, svv);
            acc[kk][1] = pk2(svv, svv);
        }
#pragma unroll 4
        for (int l = 0; l < 64; l += 2) {
            ulonglong2 p0 = *(const ulonglong2*)(bs + l * 36 + q * 4);
            ulonglong2 p1 = *(const ulonglong2*)(bs + (l + 1) * 36 + q * 4);
#pragma unroll
            for (int kk = 0; kk < 4; kk++) {
                float2 w2 = *(const float2*)(w_s + (ko * 4 + kk) * 66 + l);
                unsigned long long wa = pk2(w2.x, w2.x);
                unsigned long long wb = pk2(w2.y, w2.y);
                fma2(acc[kk][0], p0.x, wa); fma2(acc[kk][1], p0.y, wa);
                fma2(acc[kk][0], p1.x, wb); fma2(acc[kk][1], p1.y, wb);
            }
        }
#pragma unroll
        for (int kk = 0; kk < 4; kk++) {
            ulonglong2 o; o.x = acc[kk][0]; o.y = acc[kk][1];
            *(ulonglong2*)(lg + (ko * 4 + kk) * 36 + q * 4) = o;
        }
        __syncthreads();

        // ---- phase c: (b=cb, l_slot=ls), i-half = ih; pair via t^128 ----
        {
            float lv[16];
            float m16 = -3.4e38f;
#pragma unroll
            for (int i = 0; i < 16; i++) {
                lv[i] = lg[(ls * 32 + ih * 16 + i) * 36 + cb];
                m16 = fmaxf(m16, lv[i]);
            }
            pm[t] = m16;
            __syncthreads();
            float m = fmaxf(m16, pm[t ^ 128]);
            float s16 = 0.f;
#pragma unroll
            for (int i = 0; i < 16; i++) {
                lv[i] = __expf(lv[i] - m);
                s16 += lv[i];
            }
            pm[t] = s16;
            __syncthreads();
            float Z = s16 + pm[t ^ 128];
            int l = kq * 16 + ch * 4 + ls;
            float s = bs[l * 36 + cb] / Z;
#pragma unroll
            for (int i = 0; i < 16; i++) accI[i] += lv[i] * s;
        }
    }
    __syncthreads();

    // reduce 4 l_slot partials per b (reuse w_s; pad 33)
    float* red2 = w_s;
#pragma unroll
    for (int i = 0; i < 16; i++)
        red2[(ls * 32 + cb) * 33 + ih * 16 + i] = accI[i];
    __syncthreads();
#pragma unroll
    for (int r = 0; r < 4; r++) {
        int e = t * 4 + r;               // 0..1023
        int bb = e >> 5, i = e & 31;
        float s = 0.f;
#pragma unroll
        for (int l4 = 0; l4 < 4; l4++) s += red2[(l4 * 32 + bb) * 33 + i];
        g_cvp[(((size_t)kq * NJ + j) * NB + b0 + bb) * 32 + i] = s;
    }
}

// =============================================================================
// Kernel C: cv_total = body + 32 slot partials; out = conf * (cv@W^T + b)
// =============================================================================
extern "C" __global__ void __launch_bounds__(128)
kC(const float* __restrict__ head_w, const float* __restrict__ head_b,
   float* __restrict__ out)
{
    __shared__ float cvt[32];
    __shared__ float hw[NO * 33];
    const int t = threadIdx.x;
    const int b = blockIdx.x;

#pragma unroll
    for (int r = 0; r < 32; r++) {
        int e = t + 128 * r;             // 0..4095
        int o = e >> 5, i = e & 31;
        hw[o * 33 + i] = head_w[e];
    }
    if (t < 32) {
        float v = g_cv[b * 32 + t];
#pragma unroll
        for (int p = 0; p < 32; p++)
            v += g_cvp[((size_t)p * NB + b) * 32 + t];
        cvt[t] = v;
    }
    __syncthreads();

    float d = head_b[t];
#pragma unroll
    for (int i = 0; i < 32; i++) d += cvt[i] * hw[t * 33 + i];
    out[b * NO + t] = g_conf[b] * d;
}

// =============================================================================
extern "C" void kernel_launch(void* const* d_in, const int* in_sizes, int n_in,
                              void* d_out, int out_size)
{
    const float* wm  = (const float*)d_in[0];
    const float* cst = (const float*)d_in[1];
    const float* gam = (const float*)d_in[2];
    const float* bw  = (const float*)d_in[3];
    const float* bb  = (const float*)d_in[4];
    const float* sw  = (const float*)d_in[5];
    const float* sb  = (const float*)d_in[6];
    const float* hwp = (const float*)d_in[7];
    const float* hbp = (const float*)d_in[8];
    float* out = (float*)d_out;

    cudaFuncSetAttribute(kA, cudaFuncAttributeMaxDynamicSharedMemorySize,
                         A_SMEM_FLOATS * 4);
    cudaFuncSetAttribute(kB, cudaFuncAttributeMaxDynamicSharedMemorySize,
                         B_SMEM_FLOATS * 4);

    kA<<<NB, 128, A_SMEM_FLOATS * 4>>>(wm, cst, gam, bw, bb);
    dim3 gb(16, 8, 4);
    kB<<<gb, 256, B_SMEM_FLOATS * 4>>>(sw, sb);
    kC<<<NB, 128>>>(hwp, hbp, out);
}

// round 14
// speedup vs baseline: 1.8032x; 1.0171x over previous
#include <cuda_runtime.h>
#include <math.h>

// Problem shapes (fixed)
#define NB 512
#define NW 1024
#define NL 64
#define NJ 8
#define NI 32
#define NO 128
#define NK 2048   // L*I
#define NSPLIT 3  // w-splits of kA: chunks {3,3,2} x 128 w

// ---------------- device scratch (no allocations allowed) -------------------
__device__ float g_best[NJ * NB * NL];       // best[j][b][l]        (1 MB)
__device__ float g_cv  [NB * NI];            // body contribution
__device__ float g_cvp [4 * NJ * NB * NI];   // slot partials [kq][j][b][i]
__device__ float g_conf[NB];                 // exp(-total_mq)
__device__ float p_Z   [NSPLIT * NB * NJ];   // partial Z   [zi][b][j]
__device__ float p_Q   [NSPLIT * NB * NJ];   // partial sum e*s
__device__ float p_C   [NSPLIT * NB * NJ];   // per-split exp offset
__device__ float p_best[NSPLIT * NJ * NB * NL];  // raw sum e*x (3 MB)

// ---------------- packed f32x2 helpers (Blackwell FFMA2) --------------------
static __device__ __forceinline__ unsigned long long pk2(float x, float y) {
    unsigned long long r;
    asm("mov.b64 %0, {%1,%2};" : "=l"(r) : "f"(x), "f"(y));
    return r;
}
static __device__ __forceinline__ void fma2(unsigned long long& d,
                                            unsigned long long a,
                                            unsigned long long b) {
    asm("fma.rn.f32x2 %0, %1, %2, %0;" : "+l"(d) : "l"(a), "l"(b));
}
static __device__ __forceinline__ float2 up2(unsigned long long v) {
    float2 r;
    asm("mov.b64 {%0,%1}, %2;" : "=f"(r.x), "=f"(r.y) : "l"(v));
    return r;
}

// =============================================================================
// Kernel A1: partial scores/softmax/best for one (b, w-split).
// grid = (512 b, 3 zi), 128 threads. zi 0/1: chunks 0-2/3-5; zi 2: chunks 6-7.
// Score tile per thread: W=2 (wp, wp+64) x J=4 (jh*4..+3) -> 0.5 wf/FFMA2.
// Writes p_Z/p_Q/p_C and raw p_best (no normalization).
// smem ~41.9 KB -> 5 CTAs/SM; 1536 CTAs ~ 2 waves.
// =============================================================================
#define CW     128
#define A_COEF 0
#define A_TILE 1024
#define A_SCB  (A_TILE + 128*65)      // 9344
#define A_AS   (A_SCB + 1024)         // 10368
#define A_CS   (A_AS + 8)
#define A_ZW   (A_CS + 8)             // 4 warps x 4
#define A_QW   (A_ZW + 16)
#define A_SMEM_FLOATS (A_QW + 16)     // 10408

extern "C" __global__ void __launch_bounds__(128, 5)
kA1(const float* __restrict__ wm, const float* __restrict__ constants,
    const float* __restrict__ gammas)
{
    extern __shared__ float sm[];
    unsigned long long* coefT = (unsigned long long*)(sm + A_COEF); // [l*8+j]
    float* tile = sm + A_TILE;
    float* scb  = sm + A_SCB;
    float* As   = sm + A_AS;
    float* Cs   = sm + A_CS;
    float* zw   = sm + A_ZW;
    float* qw   = sm + A_QW;

    const int t    = threadIdx.x;
    const int b    = blockIdx.x;
    const int zi   = blockIdx.y;
    const int lane = t & 31;
    const int wid  = t >> 5;          // 0..3
    const int wp   = t & 63;          // score: w in {wp, wp+64}
    const int jh   = t >> 6;          // score: j in {4jh..4jh+3}

    const int s0  = zi * 3;                    // first chunk
    const int nch = (zi < 2) ? 3 : 2;          // chunk count

    // ---- Phase 0: coefficients (scratch in tile) ----
    for (int e = t; e < NJ * NL; e += 128) {
        float g = gammas[e];
        g = fminf(fmaxf(g, 0.f), 1.f);
        float w1 = 1.f - g;
        float c  = constants[e];
        int j = e >> 6, l = e & 63;
        coefT[l * 8 + j] = pk2(-2.f * w1 * c, w1);
        tile[e] = w1 * c * c;
    }
    __syncthreads();
    if (t < 8) {
        float a = 0.f;
        for (int l = 0; l < NL; l++) a += tile[t * 64 + l];
        As[t] = a;
    }
    __syncthreads();

    float Areg[4];
#pragma unroll
    for (int k = 0; k < 4; k++) Areg[k] = As[4 * jh + k];
    const ulonglong2* cT = (const ulonglong2*)coefT;   // [l*4 + 2jh (+1)]
    const float* wmb = wm + (size_t)b * (NW * NL);

    unsigned long long accP[2][4];        // best accum: [x-half][(j,j+1) pair]
#pragma unroll
    for (int h = 0; h < 2; h++)
#pragma unroll
        for (int p = 0; p < 4; p++) accP[h][p] = pk2(0.f, 0.f);
    float zp[4] = {0.f, 0.f, 0.f, 0.f};
    float qp[4] = {0.f, 0.f, 0.f, 0.f};
    float Cr[4] = {0.f, 0.f, 0.f, 0.f};   // exp offsets (set @ first chunk)

    for (int ch = s0; ch < s0 + nch; ch++) {
        __syncthreads();
        // ---- stage 128-w chunk (128 threads, 16 float4 each) ----
        const float4* src = (const float4*)(wmb + ch * CW * 64);
#pragma unroll
        for (int qq = 0; qq < 16; qq++) {
            int f = t + 128 * qq;            // 0..2047 float4s
            int row = f >> 4, c4 = f & 15;
            float4 v = src[f];
            float* dst = tile + row * 65 + c4 * 4;
            dst[0] = v.x; dst[1] = v.y; dst[2] = v.z; dst[3] = v.w;
        }
        __syncthreads();

        // ---- scores: w in {wp, wp+64}, j = 4jh..4jh+3 ----
        unsigned long long s00 = pk2(Areg[0], 0.f);
        unsigned long long s01 = pk2(Areg[1], 0.f);
        unsigned long long s02 = pk2(Areg[2], 0.f);
        unsigned long long s03 = pk2(Areg[3], 0.f);
        unsigned long long s10 = s00, s11 = s01, s12 = s02, s13 = s03;
        const float* r0 = tile + wp * 65;
        const float* r1 = tile + (wp + 64) * 65;
#pragma unroll 16
        for (int l = 0; l < 64; l++) {
            float x0 = r0[l], x1 = r1[l];
            unsigned long long a0 = pk2(x0, x0 * x0);
            unsigned long long a1 = pk2(x1, x1 * x1);
            ulonglong2 ccA = cT[l * 4 + 2 * jh];
            ulonglong2 ccB = cT[l * 4 + 2 * jh + 1];
            fma2(s00, a0, ccA.x); fma2(s01, a0, ccA.y);
            fma2(s02, a0, ccB.x); fma2(s03, a0, ccB.y);
            fma2(s10, a1, ccA.x); fma2(s11, a1, ccA.y);
            fma2(s12, a1, ccB.x); fma2(s13, a1, ccB.y);
        }
        float sv0[4], sv1[4];
        { float2 p = up2(s00); sv0[0] = p.x + p.y; }
        { float2 p = up2(s01); sv0[1] = p.x + p.y; }
        { float2 p = up2(s02); sv0[2] = p.x + p.y; }
        { float2 p = up2(s03); sv0[3] = p.x + p.y; }
        { float2 p = up2(s10); sv1[0] = p.x + p.y; }
        { float2 p = up2(s11); sv1[1] = p.x + p.y; }
        { float2 p = up2(s12); sv1[2] = p.x + p.y; }
        { float2 p = up2(s13); sv1[3] = p.x + p.y; }

        if (ch == s0) {
            // establish exp offsets C_j = min over first-chunk scores
            *(float4*)(scb + wp * 8 + 4 * jh)        = make_float4(sv0[0], sv0[1], sv0[2], sv0[3]);
            *(float4*)(scb + (wp + 64) * 8 + 4 * jh) = make_float4(sv1[0], sv1[1], sv1[2], sv1[3]);
            __syncthreads();
#pragma unroll
            for (int k = 0; k < 2; k++) {          // warp wid handles j=2wid+k
                int j = 2 * wid + k;
                float mn = 3.4e38f;
#pragma unroll
                for (int r = 0; r < 4; r++)
                    mn = fminf(mn, scb[(lane + 32 * r) * 8 + j]);
#pragma unroll
                for (int o = 16; o; o >>= 1)
                    mn = fminf(mn, __shfl_xor_sync(0xffffffffu, mn, o));
                if (lane == 0) Cs[j] = mn;
            }
            __syncthreads();
#pragma unroll
            for (int k = 0; k < 4; k++) Cr[k] = Cs[4 * jh + k];
        }

        float e0[4], e1[4];
#pragma unroll
        for (int k = 0; k < 4; k++) {
            e0[k] = __expf(Cr[k] - sv0[k]);
            e1[k] = __expf(Cr[k] - sv1[k]);
            zp[k] += e0[k] + e1[k];
            qp[k] += e0[k] * sv0[k] + e1[k] * sv1[k];
        }
        *(float4*)(scb + wp * 8 + 4 * jh)        = make_float4(e0[0], e0[1], e0[2], e0[3]);
        *(float4*)(scb + (wp + 64) * 8 + 4 * jh) = make_float4(e1[0], e1[1], e1[2], e1[3]);
        __syncthreads();

        // ---- best accumulate: warp owns 32-w slice, j-pairs packed ----
        const int w0 = wid * 32;
        const ulonglong2* arow = (const ulonglong2*)scb;
#pragma unroll 8
        for (int i = 0; i < 32; i++) {
            int wl = w0 + i;
            ulonglong2 A0 = arow[wl * 2];        // (j0,j1),(j2,j3)
            ulonglong2 A1 = arow[wl * 2 + 1];    // (j4,j5),(j6,j7)
            float x0 = tile[wl * 65 + lane];
            float x1 = tile[wl * 65 + 32 + lane];
            unsigned long long xx0 = pk2(x0, x0);
            unsigned long long xx1 = pk2(x1, x1);
            fma2(accP[0][0], A0.x, xx0); fma2(accP[0][1], A0.y, xx0);
            fma2(accP[0][2], A1.x, xx0); fma2(accP[0][3], A1.y, xx0);
            fma2(accP[1][0], A0.x, xx1); fma2(accP[1][1], A0.y, xx1);
            fma2(accP[1][2], A1.x, xx1); fma2(accP[1][3], A1.y, xx1);
        }
    }

    // ---- Z/Q reduction ----
#pragma unroll
    for (int o = 16; o; o >>= 1)
#pragma unroll
        for (int k = 0; k < 4; k++) {
            zp[k] += __shfl_xor_sync(0xffffffffu, zp[k], o);
            qp[k] += __shfl_xor_sync(0xffffffffu, qp[k], o);
        }
    __syncthreads();                       // chunk loop done; reuse tile
    if (lane == 0) {
#pragma unroll
        for (int k = 0; k < 4; k++) { zw[wid * 4 + k] = zp[k]; qw[wid * 4 + k] = qp[k]; }
    }
    // dump best partials (warp-sliced) into tile
    float* red = tile;
#pragma unroll
    for (int p = 0; p < 4; p++) {
        float2 v0 = up2(accP[0][p]);
        float2 v1 = up2(accP[1][p]);
        red[(wid * 8 + 2 * p    ) * 64 + lane]      = v0.x;
        red[(wid * 8 + 2 * p + 1) * 64 + lane]      = v0.y;
        red[(wid * 8 + 2 * p    ) * 64 + 32 + lane] = v1.x;
        red[(wid * 8 + 2 * p + 1) * 64 + 32 + lane] = v1.y;
    }
    __syncthreads();
    if (t < 8) {                   // j = t; warps {2h,2h+1} hold its zp slot
        int h = t >> 2, k = t & 3;
        float Z = zw[(2 * h) * 4 + k] + zw[(2 * h + 1) * 4 + k];
        float Q = qw[(2 * h) * 4 + k] + qw[(2 * h + 1) * 4 + k];
        int o = (zi * NB + b) * NJ + t;
        p_Z[o] = Z;
        p_Q[o] = Q;
        p_C[o] = Cs[t];
    }
    // raw best partials -> gmem (no normalization)
#pragma unroll
    for (int rep = 0; rep < 2; rep++) {
        const int j = wid + 4 * rep;
        float b0 = 0.f, b1 = 0.f;
#pragma unroll
        for (int w4 = 0; w4 < 4; w4++) {
            b0 += red[(w4 * 8 + j) * 64 + lane];
            b1 += red[(w4 * 8 + j) * 64 + 32 + lane];
        }
        size_t o = ((size_t)(zi * NJ + j) * NB + b) * 64;
        p_best[o + lane]      = b0;
        p_best[o + 32 + lane] = b1;
    }
}

// =============================================================================
// Kernel A2: combine splits -> g_best, g_conf, body path -> g_cv.
// grid = 512 (b), 128 threads.
// =============================================================================
extern "C" __global__ void __launch_bounds__(128)
kA2(const float* __restrict__ gammas, const float* __restrict__ body_w,
    const float* __restrict__ body_b)
{
    __shared__ float es[NSPLIT * 8];     // e^{C-Ci}/Z per (zi,j)
    __shared__ float smq[8];
    __shared__ float sgav[8];
    __shared__ float sbest[512];
    __shared__ float sred[256];
    __shared__ float sconf;

    const int t = threadIdx.x;
    const int b = blockIdx.x;

    if (t < 8) {
        float C0 = p_C[(0 * NB + b) * NJ + t];
        float C1 = p_C[(1 * NB + b) * NJ + t];
        float C2 = p_C[(2 * NB + b) * NJ + t];
        float C = fminf(C0, fminf(C1, C2));
        float f0 = __expf(C - C0), f1 = __expf(C - C1), f2 = __expf(C - C2);
        float Z = p_Z[(0 * NB + b) * NJ + t] * f0
                + p_Z[(1 * NB + b) * NJ + t] * f1
                + p_Z[(2 * NB + b) * NJ + t] * f2;
        float Q = p_Q[(0 * NB + b) * NJ + t] * f0
                + p_Q[(1 * NB + b) * NJ + t] * f1
                + p_Q[(2 * NB + b) * NJ + t] * f2;
        float r = 1.f / Z;
        es[0 * 8 + t] = f0 * r;
        es[1 * 8 + t] = f1 * r;
        es[2 * 8 + t] = f2 * r;
        smq[t] = Q * r;
        // g_avg
        float s = 0.f;
        for (int l = 0; l < NL; l++) {
            float g = gammas[t * 64 + l];
            s += fminf(fmaxf(g, 0.f), 1.f);
        }
        sgav[t] = s * (1.f / 64.f);
    }
    __syncthreads();
    if (t == 0) {
        float tm = 0.f;
#pragma unroll
        for (int j = 0; j < 8; j++) tm += smq[j];
        sconf = expf(-tm);
        g_conf[b] = sconf;
    }

    // combine best
#pragma unroll
    for (int r = 0; r < 4; r++) {
        int idx = t + 128 * r;             // 0..511
        int j = idx >> 6, l = idx & 63;
        float v = p_best[((size_t)(0 * NJ + j) * NB + b) * 64 + l] * es[0 * 8 + j]
                + p_best[((size_t)(1 * NJ + j) * NB + b) * 64 + l] * es[1 * 8 + j]
                + p_best[((size_t)(2 * NJ + j) * NB + b) * 64 + l] * es[2 * 8 + j];
        sbest[idx] = v;
        g_best[((size_t)j * NB + b) * 64 + l] = v;
    }
    __syncthreads();

    // body path: 256 (j,i) items over 128 threads
    float outv[2];
#pragma unroll
    for (int rep = 0; rep < 2; rep++) {
        int idx = t + 128 * rep;
        int j = idx >> 5, i = idx & 31;
        const float4* bwp = (const float4*)(body_w + (j * NI + i) * NL);
        const float4* bsp = (const float4*)(sbest + j * 64);
        float d = 0.f;
#pragma unroll
        for (int l4 = 0; l4 < 16; l4++) {
            float4 w4 = bwp[l4];
            float4 x4 = bsp[l4];
            d += x4.x * w4.x + x4.y * w4.y + x4.z * w4.z + x4.w * w4.w;
        }
        d += body_b[j * NI + i];
        outv[rep] = sgav[j] * d;
    }
#pragma unroll
    for (int rep = 0; rep < 2; rep++) sred[t + 128 * rep] = outv[rep];
    __syncthreads();
    if (t < 32) {
        float s = 0.f;
#pragma unroll
        for (int j = 0; j < 8; j++) s += sred[j * 32 + t];
        g_cv[b * 32 + t] = s;
    }
}

// =============================================================================
// Kernel B: slot selector. grid = (16 b-tiles, 8 j, 4 k-quarters), 256 thr.
// 4 chunks of 128 k per CTA. Phase b: 4k x 4b FFMA2. Phase c: ALL 256 threads
// (thread pair (t, t^128) splits the 32-i softmax, exchanging via smem).
// =============================================================================
#define B_WS  0
#define B_LG  (128*66)                 // 8448
#define B_BS  (B_LG + 128*36)          // 13056
#define B_PM  (B_BS + 64*36)           // 15360
#define B_SMEM_FLOATS (B_PM + 256)     // 15616 floats = 62464 B, occ 3

extern "C" __global__ void __launch_bounds__(256, 3)
kB(const float* __restrict__ slot_w, const float* __restrict__ slot_b)
{
    extern __shared__ float sm[];
    float* w_s = sm + B_WS;
    float* lg  = sm + B_LG;
    float* bs  = sm + B_BS;
    float* pm  = sm + B_PM;

    const int t  = threadIdx.x;
    const int j  = blockIdx.y;
    const int b0 = blockIdx.x * 32;
    const int kq = blockIdx.z;           // k-quarter (512 k each)

    const int q  = t & 7;                // phase b: b quad = q*4..q*4+3
    const int ko = t >> 3;               // phase b: k = ko*4+kk (0..127)
    const int cb = t & 31;               // phase c: b
    const int ls = (t >> 5) & 3;         // phase c: l_slot
    const int ih = t >> 7;               // phase c: i half (0/1)

    // stage best transposed: bs[l*36 + b]
    {
        int bb = t >> 3;                 // 0..31
        int l0 = (t & 7) * 8;            // 8 consecutive l
        const float4* gp = (const float4*)(&g_best[((size_t)j * NB + b0 + bb) * 64 + l0]);
        float4 v0 = gp[0], v1 = gp[1];
        bs[(l0+0)*36+bb]=v0.x; bs[(l0+1)*36+bb]=v0.y;
        bs[(l0+2)*36+bb]=v0.z; bs[(l0+3)*36+bb]=v0.w;
        bs[(l0+4)*36+bb]=v1.x; bs[(l0+5)*36+bb]=v1.y;
        bs[(l0+6)*36+bb]=v1.z; bs[(l0+7)*36+bb]=v1.w;
    }

    float accI[16];
#pragma unroll
    for (int i = 0; i < 16; i++) accI[i] = 0.f;

    const float* swj = slot_w + (size_t)j * (NK * NL) + (size_t)kq * 512 * 64;
    const float* sbj = slot_b + j * NK + kq * 512;

    for (int ch = 0; ch < 4; ch++) {
        __syncthreads();
        const float4* src = (const float4*)(swj + ch * 128 * 64);
#pragma unroll
        for (int qq = 0; qq < 8; qq++) {
            int f = t + 256 * qq;           // 0..2047
            int row = f >> 4, c4 = f & 15;
            float4 v = src[f];
            float* dst = w_s + row * 66 + c4 * 4;
            dst[0] = v.x; dst[1] = v.y; dst[2] = v.z; dst[3] = v.w;
        }
        __syncthreads();

        // ---- phase b: logits, 4k x 4b, f32x2 ----
        unsigned long long acc[4][2];
#pragma unroll
        for (int kk = 0; kk < 4; kk++) {
            float svv = sbj[ch * 128 + ko * 4 + kk];
            acc[kk][0] = pk2(svv, svv);
            acc[kk][1] = pk2(svv, svv);
        }
#pragma unroll 4
        for (int l = 0; l < 64; l += 2) {
            ulonglong2 p0 = *(const ulonglong2*)(bs + l * 36 + q * 4);
            ulonglong2 p1 = *(const ulonglong2*)(bs + (l + 1) * 36 + q * 4);
#pragma unroll
            for (int kk = 0; kk < 4; kk++) {
                float2 w2 = *(const float2*)(w_s + (ko * 4 + kk) * 66 + l);
                unsigned long long wa = pk2(w2.x, w2.x);
                unsigned long long wb = pk2(w2.y, w2.y);
                fma2(acc[kk][0], p0.x, wa); fma2(acc[kk][1], p0.y, wa);
                fma2(acc[kk][0], p1.x, wb); fma2(acc[kk][1], p1.y, wb);
            }
        }
#pragma unroll
        for (int kk = 0; kk < 4; kk++) {
            ulonglong2 o; o.x = acc[kk][0]; o.y = acc[kk][1];
            *(ulonglong2*)(lg + (ko * 4 + kk) * 36 + q * 4) = o;
        }
        __syncthreads();

        // ---- phase c: (b=cb, l_slot=ls), i-half = ih; pair via t^128 ----
        {
            float lv[16];
            float m16 = -3.4e38f;
#pragma unroll
            for (int i = 0; i < 16; i++) {
                lv[i] = lg[(ls * 32 + ih * 16 + i) * 36 + cb];
                m16 = fmaxf(m16, lv[i]);
            }
            pm[t] = m16;
            __syncthreads();
            float m = fmaxf(m16, pm[t ^ 128]);
            float s16 = 0.f;
#pragma unroll
            for (int i = 0; i < 16; i++) {
                lv[i] = __expf(lv[i] - m);
                s16 += lv[i];
            }
            pm[t] = s16;
            __syncthreads();
            float Z = s16 + pm[t ^ 128];
            int l = kq * 16 + ch * 4 + ls;
            float s = bs[l * 36 + cb] / Z;
#pragma unroll
            for (int i = 0; i < 16; i++) accI[i] += lv[i] * s;
        }
    }
    __syncthreads();

    // reduce 4 l_slot partials per b (reuse w_s; pad 33)
    float* red2 = w_s;
#pragma unroll
    for (int i = 0; i < 16; i++)
        red2[(ls * 32 + cb) * 33 + ih * 16 + i] = accI[i];
    __syncthreads();
#pragma unroll
    for (int r = 0; r < 4; r++) {
        int e = t * 4 + r;               // 0..1023
        int bb = e >> 5, i = e & 31;
        float s = 0.f;
#pragma unroll
        for (int l4 = 0; l4 < 4; l4++) s += red2[(l4 * 32 + bb) * 33 + i];
        g_cvp[(((size_t)kq * NJ + j) * NB + b0 + bb) * 32 + i] = s;
    }
}

// =============================================================================
// Kernel C: cv_total = body + 32 slot partials; out = conf * (cv@W^T + b)
// =============================================================================
extern "C" __global__ void __launch_bounds__(128)
kC(const float* __restrict__ head_w, const float* __restrict__ head_b,
   float* __restrict__ out)
{
    __shared__ float cvt[32];
    __shared__ float hw[NO * 33];
    const int t = threadIdx.x;
    const int b = blockIdx.x;

#pragma unroll
    for (int r = 0; r < 32; r++) {
        int e = t + 128 * r;             // 0..4095
        int o = e >> 5, i = e & 31;
        hw[o * 33 + i] = head_w[e];
    }
    if (t < 32) {
        float v = g_cv[b * 32 + t];
#pragma unroll
        for (int p = 0; p < 32; p++)
            v += g_cvp[((size_t)p * NB + b) * 32 + t];
        cvt[t] = v;
    }
    __syncthreads();

    float d = head_b[t];
#pragma unroll
    for (int i = 0; i < 32; i++) d += cvt[i] * hw[t * 33 + i];
    out[b * NO + t] = g_conf[b] * d;
}

// =============================================================================
extern "C" void kernel_launch(void* const* d_in, const int* in_sizes, int n_in,
                              void* d_out, int out_size)
{
    const float* wm  = (const float*)d_in[0];
    const float* cst = (const float*)d_in[1];
    const float* gam = (const float*)d_in[2];
    const float* bw  = (const float*)d_in[3];
    const float* bb  = (const float*)d_in[4];
    const float* sw  = (const float*)d_in[5];
    const float* sb  = (const float*)d_in[6];
    const float* hwp = (const float*)d_in[7];
    const float* hbp = (const float*)d_in[8];
    float* out = (float*)d_out;

    cudaFuncSetAttribute(kA1, cudaFuncAttributeMaxDynamicSharedMemorySize,
                         A_SMEM_FLOATS * 4);
    cudaFuncSetAttribute(kB, cudaFuncAttributeMaxDynamicSharedMemorySize,
                         B_SMEM_FLOATS * 4);

    dim3 ga(NB, NSPLIT);
    kA1<<<ga, 128, A_SMEM_FLOATS * 4>>>(wm, cst, gam);
    kA2<<<NB, 128>>>(gam, bw, bb);
    dim3 gb(16, 8, 4);
    kB<<<gb, 256, B_SMEM_FLOATS * 4>>>(sw, sb);
    kC<<<NB, 128>>>(hwp, hbp, out);
}